// round 1
// baseline (speedup 1.0000x reference)
#include <cuda_runtime.h>
#include <cuda_bf16.h>
#include <math.h>

// Problem constants (fixed shapes per reference)
#define N_D   4096
#define N_M   8192
#define NN    12288          // N_D + N_M
#define EE    196608
#define KHOP  4
#define HIDD  512
#define LDF   2560           // HID*(K+1)
#define NPAIR 65536

// ---------------- device scratch (sanctioned: __device__ globals) ----------
__device__ int   g_deg[NN];
__device__ float g_norm[NN];
__device__ int   g_offs[NN + 1];
__device__ int   g_cursor[NN];
__device__ int   g_csr_src[EE];
__device__ float g_csr_w[EE];
__device__ float g_feat[(size_t)NN * LDF];   // [N, HID*(K+1)]  ~126 MB
__device__ float g_h[(size_t)NN * HIDD];     // [N, HID]        ~25 MB

// ---------------- small graph-prep kernels ---------------------------------
__global__ void zero_kernel() {
    int i = blockIdx.x * blockDim.x + threadIdx.x;
    if (i < NN) { g_deg[i] = 0; g_cursor[i] = 0; }
}

__global__ void deg_kernel(const int* __restrict__ dst, int E) {
    int e = blockIdx.x * blockDim.x + threadIdx.x;
    if (e < E) atomicAdd(&g_deg[dst[e]], 1);
}

__global__ void norm_kernel() {
    int v = blockIdx.x * blockDim.x + threadIdx.x;
    if (v < NN) {
        int d = g_deg[v];
        g_norm[v] = rsqrtf((float)(d > 0 ? d : 1));
    }
}

// single-block exclusive scan over g_deg -> g_offs (N=12288, 12 tiles of 1024)
__global__ void scan_kernel() {
    __shared__ int sh[1024];
    __shared__ int carry_s;
    int t = threadIdx.x;
    if (t == 0) carry_s = 0;
    __syncthreads();
    for (int base = 0; base < NN; base += 1024) {
        int v = (base + t < NN) ? g_deg[base + t] : 0;
        sh[t] = v;
        __syncthreads();
        int x = v;
        #pragma unroll
        for (int off = 1; off < 1024; off <<= 1) {
            int y = (t >= off) ? sh[t - off] : 0;
            __syncthreads();
            x += y;
            sh[t] = x;
            __syncthreads();
        }
        int carry = carry_s;
        if (base + t < NN) g_offs[base + t] = carry + x - v; // exclusive
        __syncthreads();
        if (t == 1023) carry_s = carry + x;
        __syncthreads();
    }
    if (t == 0) g_offs[NN] = carry_s;
}

__global__ void fill_kernel(const int* __restrict__ src, const int* __restrict__ dst, int E) {
    int e = blockIdx.x * blockDim.x + threadIdx.x;
    if (e < E) {
        int d = dst[e];
        int s = src[e];
        int p = g_offs[d] + atomicAdd(&g_cursor[d], 1);
        g_csr_src[p] = s;
        g_csr_w[p]   = g_norm[s] * g_norm[d];
    }
}

// ---------------- SpMM hop: gather over CSR (no atomics) -------------------
// one block (256 threads) per destination node; thread t owns cols t and t+256
__global__ void hop_kernel(int col_in, int col_out) {
    int v = blockIdx.x;
    int t = threadIdx.x;
    int s0 = g_offs[v], s1 = g_offs[v + 1];
    __shared__ int   s_src[256];
    __shared__ float s_w[256];
    float a0 = 0.f, a1 = 0.f;
    for (int base = s0; base < s1; base += 256) {
        int n = min(256, s1 - base);
        __syncthreads();
        if (t < n) { s_src[t] = g_csr_src[base + t]; s_w[t] = g_csr_w[base + t]; }
        __syncthreads();
        for (int i = 0; i < n; i++) {
            const float* row = g_feat + (size_t)s_src[i] * LDF + col_in;
            float w = s_w[i];
            a0 += w * row[t];
            a1 += w * row[t + 256];
        }
    }
    float* orow = g_feat + (size_t)v * LDF + col_out;
    orow[t]       = a0;
    orow[t + 256] = a1;
}

// ---------------- SGEMM: C[M,ldc] = A[M,K] @ B[K,N] (+bias) ----------------
// 128x128 block tile, BK=8, 8x8 per-thread microtile, 256 threads, float4 I/O
#define BM 128
#define BN 128
#define BK 8
#define TM 8
#define TN 8

__global__ __launch_bounds__(256) void sgemm128(
    int M, int N, int K,
    const float* __restrict__ A, const float* __restrict__ B,
    float* __restrict__ C, int ldc,
    const float* __restrict__ bias)
{
    __shared__ float As[BK][BM];
    __shared__ float Bs[BK][BN];

    const int tid  = threadIdx.x;
    const int cRow = blockIdx.y, cCol = blockIdx.x;
    const int tRow = tid / (BN / TN);   // 0..15
    const int tCol = tid % (BN / TN);   // 0..15

    const float* Ab = A + (size_t)cRow * BM * K;
    const float* Bb = B + cCol * BN;
    float*       Cb = C + (size_t)cRow * BM * ldc + cCol * BN;

    const int aRow = tid >> 1, aCol = (tid & 1) * 4;       // 128x8 tile via float4
    const int bRow = tid >> 5, bCol = (tid & 31) * 4;      // 8x128 tile via float4

    float acc[TM][TN] = {};
    float regM[TM], regN[TN];

    for (int k0 = 0; k0 < K; k0 += BK) {
        float4 a = *reinterpret_cast<const float4*>(Ab + (size_t)aRow * K + k0 + aCol);
        As[aCol + 0][aRow] = a.x;
        As[aCol + 1][aRow] = a.y;
        As[aCol + 2][aRow] = a.z;
        As[aCol + 3][aRow] = a.w;
        float4 b = *reinterpret_cast<const float4*>(Bb + (size_t)(k0 + bRow) * N + bCol);
        *reinterpret_cast<float4*>(&Bs[bRow][bCol]) = b;
        __syncthreads();
        #pragma unroll
        for (int k = 0; k < BK; k++) {
            #pragma unroll
            for (int i = 0; i < TM; i++) regM[i] = As[k][tRow * TM + i];
            #pragma unroll
            for (int j = 0; j < TN; j++) regN[j] = Bs[k][tCol * TN + j];
            #pragma unroll
            for (int i = 0; i < TM; i++)
                #pragma unroll
                for (int j = 0; j < TN; j++)
                    acc[i][j] += regM[i] * regN[j];
        }
        __syncthreads();
    }

    #pragma unroll
    for (int i = 0; i < TM; i++) {
        #pragma unroll
        for (int j = 0; j < TN; j += 4) {
            int col = tCol * TN + j;
            float4 v;
            v.x = acc[i][j];     v.y = acc[i][j + 1];
            v.z = acc[i][j + 2]; v.w = acc[i][j + 3];
            if (bias) {
                const float* bp2 = bias + cCol * BN + col;
                v.x += bp2[0]; v.y += bp2[1]; v.z += bp2[2]; v.w += bp2[3];
            }
            *reinterpret_cast<float4*>(Cb + (size_t)(tRow * TM + i) * ldc + col) = v;
        }
    }
}

// ---------------- pair scoring: warp per pair -------------------------------
__global__ void pair_kernel(const int* __restrict__ dis, const int* __restrict__ mir,
                            const float* __restrict__ Wp, const float* __restrict__ bp,
                            float* __restrict__ out, int P)
{
    int warp = (blockIdx.x * blockDim.x + threadIdx.x) >> 5;
    int lane = threadIdx.x & 31;
    if (warp >= P) return;
    int di = dis[warp];
    int mi = mir[warp];  // already offset by N_D in input
    const float* hd = g_h + (size_t)di * HIDD;
    const float* hm = g_h + (size_t)mi * HIDD;
    float s = 0.f;
    #pragma unroll 4
    for (int c = lane; c < HIDD; c += 32) {
        float a = hd[c], b = hm[c];
        s += a * Wp[c] + b * Wp[HIDD + c] + (a * b) * Wp[2 * HIDD + c];
    }
    #pragma unroll
    for (int o = 16; o; o >>= 1) s += __shfl_xor_sync(0xffffffffu, s, o);
    if (lane == 0) out[warp] = 1.f / (1.f + expf(-(s + bp[0])));
}

// ---------------- launch ----------------------------------------------------
extern "C" void kernel_launch(void* const* d_in, const int* in_sizes, int n_in,
                              void* d_out, int out_size)
{
    const float* d_sim    = (const float*)d_in[0];
    const float* m_sim    = (const float*)d_in[1];
    const int*   src      = (const int*)  d_in[2];
    const int*   dst      = (const int*)  d_in[3];
    const int*   diseases = (const int*)  d_in[4];
    const int*   mirnas   = (const int*)  d_in[5];
    const float* Wd       = (const float*)d_in[6];
    const float* Wm       = (const float*)d_in[7];
    const float* Wf       = (const float*)d_in[8];
    const float* bf       = (const float*)d_in[9];
    const float* Wp       = (const float*)d_in[10];
    const float* bp       = (const float*)d_in[11];
    float*       out      = (float*)d_out;

    const int E = in_sizes[2];
    const int P = in_sizes[4];

    // device-global scratch pointers (host code can't take &__device__ directly)
    float* feat = nullptr;
    float* hbuf = nullptr;
    cudaGetSymbolAddress((void**)&feat, g_feat);
    cudaGetSymbolAddress((void**)&hbuf, g_h);

    // ---- graph prep: degree -> norm -> offsets -> CSR fill
    zero_kernel<<<(NN + 255) / 256, 256>>>();
    deg_kernel<<<(E + 255) / 256, 256>>>(dst, E);
    norm_kernel<<<(NN + 255) / 256, 256>>>();
    scan_kernel<<<1, 1024>>>();
    fill_kernel<<<(E + 255) / 256, 256>>>(src, dst, E);

    // ---- node features: X = [d_sim@Wd ; m_sim@Wm] into feat0 cols [0:512)
    {
        dim3 g(HIDD / BN, N_D / BM);
        sgemm128<<<g, 256>>>(N_D, HIDD, N_D, d_sim, Wd, feat, LDF, nullptr);
    }
    {
        dim3 g(HIDD / BN, N_M / BM);
        sgemm128<<<g, 256>>>(N_M, HIDD, N_M, m_sim, Wm, feat + (size_t)N_D * LDF, LDF, nullptr);
    }

    // ---- K hops of normalized gather-sum, concatenated along columns
    for (int hop = 0; hop < KHOP; hop++)
        hop_kernel<<<NN, 256>>>(hop * HIDD, (hop + 1) * HIDD);

    // ---- h = feat0 @ Wf + bf
    {
        dim3 g(HIDD / BN, NN / BM);
        sgemm128<<<g, 256>>>(NN, HIDD, LDF, feat, Wf, hbuf, HIDD, bf);
    }

    // ---- pair prediction with sigmoid
    pair_kernel<<<(P * 32 + 255) / 256, 256>>>(diseases, mirnas, Wp, bp, out, P);
    (void)n_in; (void)out_size;
}

// round 3
// speedup vs baseline: 2.9001x; 2.9001x over previous
#include <cuda_runtime.h>
#include <cuda_bf16.h>
#include <math.h>
#include <stdint.h>

// Problem constants (fixed shapes per reference)
#define N_D   4096
#define N_M   8192
#define NN    12288          // N_D + N_M
#define EE    196608
#define KHOP  4
#define HIDD  512
#define LDF   2560           // HID*(K+1)

// ---------------- device scratch ------------------------------------------
__device__ int   g_deg[NN];
__device__ float g_norm[NN];
__device__ int   g_offs[NN + 1];
__device__ int   g_cursor[NN];
__device__ int   g_csr_src[EE];
__device__ float g_csr_w[EE];
__device__ float g_feat[(size_t)NN * LDF];   // [N, 2560] fp32
__device__ float g_h[(size_t)NN * HIDD];     // [N, 512]  fp32
// bf16 split operand buffers (max A = 8192*8192, max B = 512*8192)
__device__ __nv_bfloat16 g_Ahi[(size_t)8192 * 8192];
__device__ __nv_bfloat16 g_Alo[(size_t)8192 * 8192];
__device__ __nv_bfloat16 g_Bhi[(size_t)512 * 8192];
__device__ __nv_bfloat16 g_Blo[(size_t)512 * 8192];

// ---------------- PTX helpers (sm_103-plain-safe: no tcgen05) --------------
__device__ __forceinline__ uint32_t smem_u32(const void* p) {
    uint32_t a;
    asm("{ .reg .u64 t; cvta.to.shared.u64 t, %1; cvt.u32.u64 %0, t; }"
        : "=r"(a) : "l"(p));
    return a;
}

__device__ __forceinline__ void cpasync16(uint32_t dst, const void* src) {
    asm volatile("cp.async.cg.shared.global [%0], [%1], 16;" :: "r"(dst), "l"(src));
}
__device__ __forceinline__ void cp_commit() {
    asm volatile("cp.async.commit_group;" ::: "memory");
}
template <int N>
__device__ __forceinline__ void cp_wait() {
    asm volatile("cp.async.wait_group %0;" :: "n"(N) : "memory");
}

__device__ __forceinline__ void ldsm_x4(uint32_t addr, uint32_t& r0, uint32_t& r1,
                                        uint32_t& r2, uint32_t& r3) {
    asm volatile("ldmatrix.sync.aligned.m8n8.x4.shared.b16 {%0,%1,%2,%3}, [%4];"
                 : "=r"(r0), "=r"(r1), "=r"(r2), "=r"(r3) : "r"(addr));
}

__device__ __forceinline__ void mma16816(float* c, const uint32_t* a, const uint32_t* b) {
    asm volatile(
        "mma.sync.aligned.m16n8k16.row.col.f32.bf16.bf16.f32 "
        "{%0,%1,%2,%3}, {%4,%5,%6,%7}, {%8,%9}, {%0,%1,%2,%3};"
        : "+f"(c[0]), "+f"(c[1]), "+f"(c[2]), "+f"(c[3])
        : "r"(a[0]), "r"(a[1]), "r"(a[2]), "r"(a[3]), "r"(b[0]), "r"(b[1]));
}

// ---------------- small graph-prep kernels ---------------------------------
__global__ void zero_kernel() {
    int i = blockIdx.x * blockDim.x + threadIdx.x;
    if (i < NN) { g_deg[i] = 0; g_cursor[i] = 0; }
}

__global__ void deg_kernel(const int* __restrict__ dst, int E) {
    int e = blockIdx.x * blockDim.x + threadIdx.x;
    if (e < E) atomicAdd(&g_deg[dst[e]], 1);
}

__global__ void norm_kernel() {
    int v = blockIdx.x * blockDim.x + threadIdx.x;
    if (v < NN) {
        int d = g_deg[v];
        g_norm[v] = rsqrtf((float)(d > 0 ? d : 1));
    }
}

__global__ void scan_kernel() {
    __shared__ int sh[1024];
    __shared__ int carry_s;
    int t = threadIdx.x;
    if (t == 0) carry_s = 0;
    __syncthreads();
    for (int base = 0; base < NN; base += 1024) {
        int v = (base + t < NN) ? g_deg[base + t] : 0;
        sh[t] = v;
        __syncthreads();
        int x = v;
        #pragma unroll
        for (int off = 1; off < 1024; off <<= 1) {
            int y = (t >= off) ? sh[t - off] : 0;
            __syncthreads();
            x += y;
            sh[t] = x;
            __syncthreads();
        }
        int carry = carry_s;
        if (base + t < NN) g_offs[base + t] = carry + x - v;
        __syncthreads();
        if (t == 1023) carry_s = carry + x;
        __syncthreads();
    }
    if (t == 0) g_offs[NN] = carry_s;
}

__global__ void fill_kernel(const int* __restrict__ src, const int* __restrict__ dst, int E) {
    int e = blockIdx.x * blockDim.x + threadIdx.x;
    if (e < E) {
        int d = dst[e];
        int s = src[e];
        int p = g_offs[d] + atomicAdd(&g_cursor[d], 1);
        g_csr_src[p] = s;
        g_csr_w[p]   = g_norm[s] * g_norm[d];
    }
}

// ---------------- SpMM hop: gather over CSR (no atomics) -------------------
__global__ void hop_kernel(int col_in, int col_out) {
    int v = blockIdx.x;
    int t = threadIdx.x;
    int s0 = g_offs[v], s1 = g_offs[v + 1];
    __shared__ int   s_src[256];
    __shared__ float s_w[256];
    float a0 = 0.f, a1 = 0.f;
    for (int base = s0; base < s1; base += 256) {
        int n = min(256, s1 - base);
        __syncthreads();
        if (t < n) { s_src[t] = g_csr_src[base + t]; s_w[t] = g_csr_w[base + t]; }
        __syncthreads();
        for (int i = 0; i < n; i++) {
            const float* row = g_feat + (size_t)s_src[i] * LDF + col_in;
            float w = s_w[i];
            a0 += w * row[t];
            a1 += w * row[t + 256];
        }
    }
    float* orow = g_feat + (size_t)v * LDF + col_out;
    orow[t]       = a0;
    orow[t + 256] = a1;
}

// ---------------- fp32 -> bf16 hi/lo split (row-major copy) ----------------
__global__ void splitA_kernel(const float* __restrict__ A,
                              __nv_bfloat16* __restrict__ hi,
                              __nv_bfloat16* __restrict__ lo, int n4)
{
    int i = blockIdx.x * blockDim.x + threadIdx.x;
    if (i >= n4) return;
    float4 v = reinterpret_cast<const float4*>(A)[i];
    float xs[4] = {v.x, v.y, v.z, v.w};
    uint2 ph, pl;
    __nv_bfloat16* hp = reinterpret_cast<__nv_bfloat16*>(&ph);
    __nv_bfloat16* lp = reinterpret_cast<__nv_bfloat16*>(&pl);
    #pragma unroll
    for (int j = 0; j < 4; j++) {
        __nv_bfloat16 h = __float2bfloat16(xs[j]);
        hp[j] = h;
        lp[j] = __float2bfloat16(xs[j] - __bfloat162float(h));
    }
    reinterpret_cast<uint2*>(hi)[i] = ph;
    reinterpret_cast<uint2*>(lo)[i] = pl;
}

// ---------------- fp32 W[K,512] -> bf16 hi/lo transposed [512,K] -----------
__global__ void splitBT_kernel(const float* __restrict__ W, int K,
                               __nv_bfloat16* __restrict__ hi,
                               __nv_bfloat16* __restrict__ lo)
{
    __shared__ float t[32][33];
    int n0 = blockIdx.x * 32;
    int k0 = blockIdx.y * 32;
    int tx = threadIdx.x, ty = threadIdx.y;  // 32 x 8
    #pragma unroll
    for (int r = 0; r < 32; r += 8)
        t[ty + r][tx] = W[(size_t)(k0 + ty + r) * HIDD + n0 + tx];
    __syncthreads();
    #pragma unroll
    for (int r = 0; r < 32; r += 8) {
        float x = t[tx][ty + r];
        __nv_bfloat16 h = __float2bfloat16(x);
        __nv_bfloat16 l = __float2bfloat16(x - __bfloat162float(h));
        size_t o = (size_t)(n0 + ty + r) * K + k0 + tx;
        hi[o] = h;
        lo[o] = l;
    }
}

// ---------------- HMMA bf16x3 GEMM ------------------------------------------
// C[M,ldc](fp32) = A[M,K] @ W[K,512], operands pre-split hi/lo bf16, W pre-
// transposed to [512,K]. Block tile 128x128x32, 3-stage cp.async pipeline,
// 8 warps (4Mx2N), warp tile 32x64, mma.sync m16n8k16 bf16, 3 split MMAs.
#define GSTAGES 3
#define TILE_B   8192                 // one 128x32 bf16 tile
#define STAGE_B  (4 * TILE_B)         // Ahi,Alo,Bhi,Blo
#define GEMM_SMEM (GSTAGES * STAGE_B) // 96 KB

__global__ __launch_bounds__(256, 1) void gemm_bf16x3(
    const __nv_bfloat16* __restrict__ Ahi, const __nv_bfloat16* __restrict__ Alo,
    const __nv_bfloat16* __restrict__ Bhi, const __nv_bfloat16* __restrict__ Blo,
    int K, float* __restrict__ C, int ldc, const float* __restrict__ bias)
{
    extern __shared__ char dynsm[];
    const uint32_t sbase = smem_u32(dynsm);

    const int tid = threadIdx.x;
    const int wid = tid >> 5;
    const int lid = tid & 31;
    const int wm  = wid >> 1;          // 0..3 -> M offset wm*32
    const int wn  = wid & 1;           // 0..1 -> N offset wn*64
    const int mbase = blockIdx.y * 128;
    const int nb0   = blockIdx.x * 128;

    const __nv_bfloat16* gsrc[4] = {
        Ahi + (size_t)mbase * K, Alo + (size_t)mbase * K,
        Bhi + (size_t)nb0 * K,   Blo + (size_t)nb0 * K };

    const int chunks = K >> 5;     // 32 bf16 per chunk

    // ---- stage loader: 4 tiles x (128 rows x 64B), 2 x 16B per thread/tile
    auto load_stage = [&](int stage, int c) {
        const int k0 = c << 5;
        const uint32_t sb = sbase + stage * STAGE_B;
        #pragma unroll
        for (int T = 0; T < 4; T++) {
            #pragma unroll
            for (int i = 0; i < 2; i++) {
                int idx = tid + (i << 8);
                int row = idx >> 2, ch = idx & 3;
                uint32_t sw = (uint32_t)(ch ^ ((row >> 1) & 3));
                cpasync16(sb + T * TILE_B + row * 64 + (sw << 4),
                          gsrc[T] + (size_t)row * K + k0 + ch * 8);
            }
        }
    };

    float acc[2][8][4] = {};

    // prologue: fill first GSTAGES-1 stages
    #pragma unroll
    for (int s = 0; s < GSTAGES - 1; s++) {
        load_stage(s, s);
        cp_commit();
    }

    for (int c = 0; c < chunks; c++) {
        const int cl = c + GSTAGES - 1;
        if (cl < chunks) load_stage(cl % GSTAGES, cl);
        cp_commit();
        cp_wait<GSTAGES - 1>();
        __syncthreads();

        const uint32_t sb = sbase + (c % GSTAGES) * STAGE_B;
        #pragma unroll
        for (int ks = 0; ks < 2; ks++) {
            uint32_t aH[2][4], aL[2][4], bH[8][2], bL[8][2];
            #pragma unroll
            for (int mt = 0; mt < 2; mt++) {
                int row = wm * 32 + mt * 16 + (lid & 15);
                int ch  = ks * 2 + (lid >> 4);
                uint32_t off = row * 64 + ((uint32_t)(ch ^ ((row >> 1) & 3)) << 4);
                ldsm_x4(sb + off,          aH[mt][0], aH[mt][1], aH[mt][2], aH[mt][3]);
                ldsm_x4(sb + TILE_B + off, aL[mt][0], aL[mt][1], aL[mt][2], aL[mt][3]);
            }
            #pragma unroll
            for (int nt2 = 0; nt2 < 4; nt2++) {
                int row = wn * 64 + nt2 * 16 + (lid & 7) + ((lid >> 4) << 3);
                int ch  = ks * 2 + ((lid >> 3) & 1);
                uint32_t off = row * 64 + ((uint32_t)(ch ^ ((row >> 1) & 3)) << 4);
                ldsm_x4(sb + 2 * TILE_B + off,
                        bH[2*nt2][0], bH[2*nt2][1], bH[2*nt2+1][0], bH[2*nt2+1][1]);
                ldsm_x4(sb + 3 * TILE_B + off,
                        bL[2*nt2][0], bL[2*nt2][1], bL[2*nt2+1][0], bL[2*nt2+1][1]);
            }
            #pragma unroll
            for (int mt = 0; mt < 2; mt++) {
                #pragma unroll
                for (int nt = 0; nt < 8; nt++) {
                    mma16816(acc[mt][nt], aH[mt], bH[nt]);
                    mma16816(acc[mt][nt], aH[mt], bL[nt]);
                    mma16816(acc[mt][nt], aL[mt], bH[nt]);
                }
            }
        }
        __syncthreads();
    }

    // ---- epilogue
    const int gid = lid >> 2, tig = lid & 3;
    #pragma unroll
    for (int mt = 0; mt < 2; mt++) {
        #pragma unroll
        for (int nt = 0; nt < 8; nt++) {
            int r0  = mbase + wm * 32 + mt * 16 + gid;
            int col = nb0 + wn * 64 + nt * 8 + tig * 2;
            float2 v0 = make_float2(acc[mt][nt][0], acc[mt][nt][1]);
            float2 v1 = make_float2(acc[mt][nt][2], acc[mt][nt][3]);
            if (bias) {
                float2 bb = *reinterpret_cast<const float2*>(bias + col);
                v0.x += bb.x; v0.y += bb.y;
                v1.x += bb.x; v1.y += bb.y;
            }
            *reinterpret_cast<float2*>(C + (size_t)r0 * ldc + col)       = v0;
            *reinterpret_cast<float2*>(C + (size_t)(r0 + 8) * ldc + col) = v1;
        }
    }
}

// ---------------- pair scoring: warp per pair -------------------------------
__global__ void pair_kernel(const int* __restrict__ dis, const int* __restrict__ mir,
                            const float* __restrict__ Wp, const float* __restrict__ bp,
                            float* __restrict__ out, int P)
{
    int warp = (blockIdx.x * blockDim.x + threadIdx.x) >> 5;
    int lane = threadIdx.x & 31;
    if (warp >= P) return;
    int di = dis[warp];
    int mi = mir[warp];
    const float* hd = g_h + (size_t)di * HIDD;
    const float* hm = g_h + (size_t)mi * HIDD;
    float s = 0.f;
    #pragma unroll 4
    for (int c = lane; c < HIDD; c += 32) {
        float a = hd[c], b = hm[c];
        s += a * Wp[c] + b * Wp[HIDD + c] + (a * b) * Wp[2 * HIDD + c];
    }
    #pragma unroll
    for (int o = 16; o; o >>= 1) s += __shfl_xor_sync(0xffffffffu, s, o);
    if (lane == 0) out[warp] = 1.f / (1.f + expf(-(s + bp[0])));
}

// ---------------- launch ----------------------------------------------------
extern "C" void kernel_launch(void* const* d_in, const int* in_sizes, int n_in,
                              void* d_out, int out_size)
{
    const float* d_sim    = (const float*)d_in[0];
    const float* m_sim    = (const float*)d_in[1];
    const int*   src      = (const int*)  d_in[2];
    const int*   dst      = (const int*)  d_in[3];
    const int*   diseases = (const int*)  d_in[4];
    const int*   mirnas   = (const int*)  d_in[5];
    const float* Wd       = (const float*)d_in[6];
    const float* Wm       = (const float*)d_in[7];
    const float* Wf       = (const float*)d_in[8];
    const float* bf       = (const float*)d_in[9];
    const float* Wp       = (const float*)d_in[10];
    const float* bp       = (const float*)d_in[11];
    float*       out      = (float*)d_out;

    const int E = in_sizes[2];
    const int P = in_sizes[4];

    float* feat = nullptr;  float* hbuf = nullptr;
    __nv_bfloat16 *Ahi = nullptr, *Alo = nullptr, *Bhi = nullptr, *Blo = nullptr;
    cudaGetSymbolAddress((void**)&feat, g_feat);
    cudaGetSymbolAddress((void**)&hbuf, g_h);
    cudaGetSymbolAddress((void**)&Ahi, g_Ahi);
    cudaGetSymbolAddress((void**)&Alo, g_Alo);
    cudaGetSymbolAddress((void**)&Bhi, g_Bhi);
    cudaGetSymbolAddress((void**)&Blo, g_Blo);

    cudaFuncSetAttribute(gemm_bf16x3,
                         cudaFuncAttributeMaxDynamicSharedMemorySize, GEMM_SMEM);

    // ---- graph prep
    zero_kernel<<<(NN + 255) / 256, 256>>>();
    deg_kernel<<<(E + 255) / 256, 256>>>(dst, E);
    norm_kernel<<<(NN + 255) / 256, 256>>>();
    scan_kernel<<<1, 1024>>>();
    fill_kernel<<<(E + 255) / 256, 256>>>(src, dst, E);

    dim3 tb(32, 8);

    // ---- X_d = d_sim @ Wd  -> feat[0:4096, 0:512)
    splitA_kernel<<<(N_D * N_D / 4 + 255) / 256, 256>>>(d_sim, Ahi, Alo, N_D * N_D / 4);
    splitBT_kernel<<<dim3(HIDD / 32, N_D / 32), tb>>>(Wd, N_D, Bhi, Blo);
    gemm_bf16x3<<<dim3(4, N_D / 128), 256, GEMM_SMEM>>>(
        Ahi, Alo, Bhi, Blo, N_D, feat, LDF, nullptr);

    // ---- X_m = m_sim @ Wm -> feat[4096:12288, 0:512)
    splitA_kernel<<<(N_M * N_M / 4 + 255) / 256, 256>>>(m_sim, Ahi, Alo, N_M * N_M / 4);
    splitBT_kernel<<<dim3(HIDD / 32, N_M / 32), tb>>>(Wm, N_M, Bhi, Blo);
    gemm_bf16x3<<<dim3(4, N_M / 128), 256, GEMM_SMEM>>>(
        Ahi, Alo, Bhi, Blo, N_M, feat + (size_t)N_D * LDF, LDF, nullptr);

    // ---- K hops of normalized gather-sum (fp32, concat along columns)
    for (int hop = 0; hop < KHOP; hop++)
        hop_kernel<<<NN, 256>>>(hop * HIDD, (hop + 1) * HIDD);

    // ---- h = feat @ Wf + bf
    splitA_kernel<<<((int)((size_t)NN * LDF / 4) + 255) / 256, 256>>>(
        feat, Ahi, Alo, (int)((size_t)NN * LDF / 4));
    splitBT_kernel<<<dim3(HIDD / 32, LDF / 32), tb>>>(Wf, LDF, Bhi, Blo);
    gemm_bf16x3<<<dim3(4, NN / 128), 256, GEMM_SMEM>>>(
        Ahi, Alo, Bhi, Blo, LDF, hbuf, HIDD, bf);

    // ---- pair prediction with sigmoid
    pair_kernel<<<(P * 32 + 255) / 256, 256>>>(diseases, mirnas, Wp, bp, out, P);
    (void)n_in; (void)out_size;
}

// round 4
// speedup vs baseline: 3.0942x; 1.0669x over previous
#include <cuda_runtime.h>
#include <cuda_bf16.h>
#include <math.h>
#include <stdint.h>

// Problem constants (fixed shapes per reference)
#define N_D   4096
#define N_M   8192
#define NN    12288          // N_D + N_M
#define EE    196608
#define KHOP  4
#define HIDD  512
#define LDF   2560           // HID*(K+1)

// ---------------- device scratch ------------------------------------------
__device__ int   g_deg[NN];
__device__ float g_norm[NN];
__device__ int   g_offs[NN + 1];
__device__ int   g_cursor[NN];
__device__ int   g_csr_src[EE];
__device__ float g_csr_w[EE];
__device__ float g_feat[(size_t)NN * LDF];   // [N, 2560] fp32
__device__ float g_h[(size_t)NN * HIDD];     // [N, 512]  fp32
// bf16 split buffers
__device__ __nv_bfloat16 g_Ahi[(size_t)8192 * 8192];   // sim matrices hi
__device__ __nv_bfloat16 g_Alo[(size_t)8192 * 8192];   // sim matrices lo
__device__ __nv_bfloat16 g_Bhi[(size_t)512 * 8192];    // transposed weights hi
__device__ __nv_bfloat16 g_Blo[(size_t)512 * 8192];    // transposed weights lo
__device__ __nv_bfloat16 g_Fhi[(size_t)NN * LDF];      // feat split hi
__device__ __nv_bfloat16 g_Flo[(size_t)NN * LDF];      // feat split lo

// ---------------- PTX helpers (plain sm_103-safe: no tcgen05) ---------------
__device__ __forceinline__ uint32_t smem_u32(const void* p) {
    uint32_t a;
    asm("{ .reg .u64 t; cvta.to.shared.u64 t, %1; cvt.u32.u64 %0, t; }"
        : "=r"(a) : "l"(p));
    return a;
}

__device__ __forceinline__ void cpasync16(uint32_t dst, const void* src) {
    asm volatile("cp.async.cg.shared.global [%0], [%1], 16;" :: "r"(dst), "l"(src));
}
__device__ __forceinline__ void cp_commit() {
    asm volatile("cp.async.commit_group;" ::: "memory");
}
template <int N>
__device__ __forceinline__ void cp_wait() {
    asm volatile("cp.async.wait_group %0;" :: "n"(N) : "memory");
}

__device__ __forceinline__ void ldsm_x4(uint32_t addr, uint32_t& r0, uint32_t& r1,
                                        uint32_t& r2, uint32_t& r3) {
    asm volatile("ldmatrix.sync.aligned.m8n8.x4.shared.b16 {%0,%1,%2,%3}, [%4];"
                 : "=r"(r0), "=r"(r1), "=r"(r2), "=r"(r3) : "r"(addr));
}

__device__ __forceinline__ void mma16816(float* c, const uint32_t* a, const uint32_t* b) {
    asm volatile(
        "mma.sync.aligned.m16n8k16.row.col.f32.bf16.bf16.f32 "
        "{%0,%1,%2,%3}, {%4,%5,%6,%7}, {%8,%9}, {%0,%1,%2,%3};"
        : "+f"(c[0]), "+f"(c[1]), "+f"(c[2]), "+f"(c[3])
        : "r"(a[0]), "r"(a[1]), "r"(a[2]), "r"(a[3]), "r"(b[0]), "r"(b[1]));
}

// ---------------- graph-prep kernels ---------------------------------------
__global__ void zero_kernel() {
    int i = blockIdx.x * blockDim.x + threadIdx.x;
    if (i < NN) { g_deg[i] = 0; g_cursor[i] = 0; }
}

__global__ void deg_kernel(const int* __restrict__ dst, int E) {
    int e = blockIdx.x * blockDim.x + threadIdx.x;
    if (e < E) atomicAdd(&g_deg[dst[e]], 1);
}

// fused norm + exclusive scan (single block, warp-shuffle hierarchy)
__global__ __launch_bounds__(1024) void normscan_kernel() {
    int tid = threadIdx.x;
    int lane = tid & 31, wid = tid >> 5;
    int vals[12];
    int base = tid * 12;
    int s = 0;
    #pragma unroll
    for (int j = 0; j < 12; j++) { vals[j] = g_deg[base + j]; s += vals[j]; }
    int x = s;
    #pragma unroll
    for (int o = 1; o < 32; o <<= 1) {
        int y = __shfl_up_sync(0xffffffffu, x, o);
        if (lane >= o) x += y;
    }
    __shared__ int wsum[32];
    if (lane == 31) wsum[wid] = x;
    __syncthreads();
    if (wid == 0) {
        int w = wsum[lane];
        #pragma unroll
        for (int o = 1; o < 32; o <<= 1) {
            int y = __shfl_up_sync(0xffffffffu, w, o);
            if (lane >= o) w += y;
        }
        wsum[lane] = w;
    }
    __syncthreads();
    int run = x - s + (wid ? wsum[wid - 1] : 0);
    #pragma unroll
    for (int j = 0; j < 12; j++) { g_offs[base + j] = run; run += vals[j]; }
    if (tid == 1023) g_offs[NN] = run;
    for (int i = tid; i < NN; i += 1024) {
        int d = g_deg[i];
        g_norm[i] = rsqrtf((float)(d > 0 ? d : 1));
    }
}

__global__ void fill_kernel(const int* __restrict__ src, const int* __restrict__ dst, int E) {
    int e = blockIdx.x * blockDim.x + threadIdx.x;
    if (e < E) {
        int d = dst[e];
        int s = src[e];
        int p = g_offs[d] + atomicAdd(&g_cursor[d], 1);
        g_csr_src[p] = s;
        g_csr_w[p]   = g_norm[s] * g_norm[d];
    }
}

// ---------------- SpMM hop: gather over CSR; emits fp32 + bf16 split --------
__global__ void hop_kernel(int col_in, int col_out, int write_f32) {
    int v = blockIdx.x;
    int t = threadIdx.x;
    int s0 = g_offs[v], s1 = g_offs[v + 1];
    __shared__ int   s_src[256];
    __shared__ float s_w[256];
    float a0 = 0.f, a1 = 0.f;
    for (int base = s0; base < s1; base += 256) {
        int n = min(256, s1 - base);
        __syncthreads();
        if (t < n) { s_src[t] = g_csr_src[base + t]; s_w[t] = g_csr_w[base + t]; }
        __syncthreads();
        for (int i = 0; i < n; i++) {
            const float2* row = reinterpret_cast<const float2*>(
                g_feat + (size_t)s_src[i] * LDF + col_in);
            float w = s_w[i];
            float2 p = row[t];
            a0 += w * p.x;
            a1 += w * p.y;
        }
    }
    size_t o = (size_t)v * LDF + col_out + 2 * t;
    if (write_f32)
        *reinterpret_cast<float2*>(g_feat + o) = make_float2(a0, a1);
    __nv_bfloat16 h0 = __float2bfloat16(a0);
    __nv_bfloat16 h1 = __float2bfloat16(a1);
    __nv_bfloat162 hv; hv.x = h0; hv.y = h1;
    __nv_bfloat162 lv;
    lv.x = __float2bfloat16(a0 - __bfloat162float(h0));
    lv.y = __float2bfloat16(a1 - __bfloat162float(h1));
    *reinterpret_cast<__nv_bfloat162*>(g_Fhi + o) = hv;
    *reinterpret_cast<__nv_bfloat162*>(g_Flo + o) = lv;
}

// ---------------- fp32 -> bf16 hi/lo split (row-major copy) ----------------
__global__ void splitA_kernel(const float* __restrict__ A,
                              __nv_bfloat16* __restrict__ hi,
                              __nv_bfloat16* __restrict__ lo, int n4)
{
    int i = blockIdx.x * blockDim.x + threadIdx.x;
    if (i >= n4) return;
    float4 v = reinterpret_cast<const float4*>(A)[i];
    float xs[4] = {v.x, v.y, v.z, v.w};
    uint2 ph, pl;
    __nv_bfloat16* hp = reinterpret_cast<__nv_bfloat16*>(&ph);
    __nv_bfloat16* lp = reinterpret_cast<__nv_bfloat16*>(&pl);
    #pragma unroll
    for (int j = 0; j < 4; j++) {
        __nv_bfloat16 h = __float2bfloat16(xs[j]);
        hp[j] = h;
        lp[j] = __float2bfloat16(xs[j] - __bfloat162float(h));
    }
    reinterpret_cast<uint2*>(hi)[i] = ph;
    reinterpret_cast<uint2*>(lo)[i] = pl;
}

// ---------------- fp32 W[K,512] -> bf16 hi/lo transposed [512,K] -----------
__global__ void splitBT_kernel(const float* __restrict__ W, int K,
                               __nv_bfloat16* __restrict__ hi,
                               __nv_bfloat16* __restrict__ lo)
{
    __shared__ float t[32][33];
    int n0 = blockIdx.x * 32;
    int k0 = blockIdx.y * 32;
    int tx = threadIdx.x, ty = threadIdx.y;  // 32 x 8
    #pragma unroll
    for (int r = 0; r < 32; r += 8)
        t[ty + r][tx] = W[(size_t)(k0 + ty + r) * HIDD + n0 + tx];
    __syncthreads();
    #pragma unroll
    for (int r = 0; r < 32; r += 8) {
        float x = t[tx][ty + r];
        __nv_bfloat16 h = __float2bfloat16(x);
        __nv_bfloat16 l = __float2bfloat16(x - __bfloat162float(h));
        size_t o = (size_t)(n0 + ty + r) * K + k0 + tx;
        hi[o] = h;
        lo[o] = l;
    }
}

// ---------------- HMMA bf16x3 GEMM ------------------------------------------
// C[M,ldc](fp32) = A[M,K] @ W[K,512] with pre-split bf16 operands, W pre-
// transposed. Block tile 128x128x32, 4-stage cp.async pipeline, one barrier
// per chunk, 8 warps (4Mx2N), warp tile 32x64, mma.sync m16n8k16 x3 splits.
// Optionally also writes the bf16 hi/lo split of C (for feat production).
#define GSTAGES 4
#define TILE_B   8192                 // one 128x32 bf16 tile
#define STAGE_B  (4 * TILE_B)         // Ahi,Alo,Bhi,Blo
#define GEMM_SMEM (GSTAGES * STAGE_B) // 128 KB

__global__ __launch_bounds__(256, 1) void gemm_bf16x3(
    const __nv_bfloat16* __restrict__ Ahi, const __nv_bfloat16* __restrict__ Alo,
    const __nv_bfloat16* __restrict__ Bhi, const __nv_bfloat16* __restrict__ Blo,
    int K, float* __restrict__ C, int ldc, const float* __restrict__ bias,
    __nv_bfloat16* __restrict__ Chi, __nv_bfloat16* __restrict__ Clo, int ldc2)
{
    extern __shared__ char dynsm[];
    const uint32_t sbase = smem_u32(dynsm);

    const int tid = threadIdx.x;
    const int wid = tid >> 5;
    const int lid = tid & 31;
    const int wm  = wid >> 1;
    const int wn  = wid & 1;
    const int mbase = blockIdx.y * 128;
    const int nb0   = blockIdx.x * 128;

    const __nv_bfloat16* gsrc[4] = {
        Ahi + (size_t)mbase * K, Alo + (size_t)mbase * K,
        Bhi + (size_t)nb0 * K,   Blo + (size_t)nb0 * K };

    const int chunks = K >> 5;

    auto load_stage = [&](int stage, int c) {
        const int k0 = c << 5;
        const uint32_t sb = sbase + stage * STAGE_B;
        #pragma unroll
        for (int T = 0; T < 4; T++) {
            #pragma unroll
            for (int i = 0; i < 2; i++) {
                int idx = tid + (i << 8);
                int row = idx >> 2, ch = idx & 3;
                uint32_t sw = (uint32_t)(ch ^ ((row >> 1) & 3));
                cpasync16(sb + T * TILE_B + row * 64 + (sw << 4),
                          gsrc[T] + (size_t)row * K + k0 + ch * 8);
            }
        }
    };

    float acc[2][8][4] = {};

    #pragma unroll
    for (int s = 0; s < GSTAGES - 1; s++) { load_stage(s, s); cp_commit(); }

    for (int c = 0; c < chunks; c++) {
        cp_wait<GSTAGES - 2>();
        __syncthreads();
        const int cl = c + GSTAGES - 1;
        if (cl < chunks) load_stage(cl % GSTAGES, cl);
        cp_commit();

        const uint32_t sb = sbase + (c % GSTAGES) * STAGE_B;
        #pragma unroll
        for (int ks = 0; ks < 2; ks++) {
            uint32_t aH[2][4], aL[2][4], bH[8][2], bL[8][2];
            #pragma unroll
            for (int mt = 0; mt < 2; mt++) {
                int row = wm * 32 + mt * 16 + (lid & 15);
                int ch  = ks * 2 + (lid >> 4);
                uint32_t off = row * 64 + ((uint32_t)(ch ^ ((row >> 1) & 3)) << 4);
                ldsm_x4(sb + off,          aH[mt][0], aH[mt][1], aH[mt][2], aH[mt][3]);
                ldsm_x4(sb + TILE_B + off, aL[mt][0], aL[mt][1], aL[mt][2], aL[mt][3]);
            }
            #pragma unroll
            for (int nt2 = 0; nt2 < 4; nt2++) {
                int row = wn * 64 + nt2 * 16 + (lid & 7) + ((lid >> 4) << 3);
                int ch  = ks * 2 + ((lid >> 3) & 1);
                uint32_t off = row * 64 + ((uint32_t)(ch ^ ((row >> 1) & 3)) << 4);
                ldsm_x4(sb + 2 * TILE_B + off,
                        bH[2*nt2][0], bH[2*nt2][1], bH[2*nt2+1][0], bH[2*nt2+1][1]);
                ldsm_x4(sb + 3 * TILE_B + off,
                        bL[2*nt2][0], bL[2*nt2][1], bL[2*nt2+1][0], bL[2*nt2+1][1]);
            }
            #pragma unroll
            for (int mt = 0; mt < 2; mt++) {
                #pragma unroll
                for (int nt = 0; nt < 8; nt++) {
                    mma16816(acc[mt][nt], aH[mt], bH[nt]);
                    mma16816(acc[mt][nt], aH[mt], bL[nt]);
                    mma16816(acc[mt][nt], aL[mt], bH[nt]);
                }
            }
        }
    }

    // ---- epilogue
    const int gid = lid >> 2, tig = lid & 3;
    #pragma unroll
    for (int mt = 0; mt < 2; mt++) {
        #pragma unroll
        for (int nt = 0; nt < 8; nt++) {
            int r0  = mbase + wm * 32 + mt * 16 + gid;
            int col = nb0 + wn * 64 + nt * 8 + tig * 2;
            float2 v0 = make_float2(acc[mt][nt][0], acc[mt][nt][1]);
            float2 v1 = make_float2(acc[mt][nt][2], acc[mt][nt][3]);
            if (bias) {
                float2 bb = *reinterpret_cast<const float2*>(bias + col);
                v0.x += bb.x; v0.y += bb.y;
                v1.x += bb.x; v1.y += bb.y;
            }
            *reinterpret_cast<float2*>(C + (size_t)r0 * ldc + col)       = v0;
            *reinterpret_cast<float2*>(C + (size_t)(r0 + 8) * ldc + col) = v1;
            if (Chi) {
                __nv_bfloat162 h0, l0, h1, l1;
                h0.x = __float2bfloat16(v0.x);
                h0.y = __float2bfloat16(v0.y);
                l0.x = __float2bfloat16(v0.x - __bfloat162float(h0.x));
                l0.y = __float2bfloat16(v0.y - __bfloat162float(h0.y));
                h1.x = __float2bfloat16(v1.x);
                h1.y = __float2bfloat16(v1.y);
                l1.x = __float2bfloat16(v1.x - __bfloat162float(h1.x));
                l1.y = __float2bfloat16(v1.y - __bfloat162float(h1.y));
                *reinterpret_cast<__nv_bfloat162*>(Chi + (size_t)r0 * ldc2 + col)       = h0;
                *reinterpret_cast<__nv_bfloat162*>(Clo + (size_t)r0 * ldc2 + col)       = l0;
                *reinterpret_cast<__nv_bfloat162*>(Chi + (size_t)(r0 + 8) * ldc2 + col) = h1;
                *reinterpret_cast<__nv_bfloat162*>(Clo + (size_t)(r0 + 8) * ldc2 + col) = l1;
            }
        }
    }
}

// ---------------- pair scoring: warp per pair -------------------------------
__global__ void pair_kernel(const int* __restrict__ dis, const int* __restrict__ mir,
                            const float* __restrict__ Wp, const float* __restrict__ bp,
                            float* __restrict__ out, int P)
{
    int warp = (blockIdx.x * blockDim.x + threadIdx.x) >> 5;
    int lane = threadIdx.x & 31;
    if (warp >= P) return;
    int di = dis[warp];
    int mi = mir[warp];
    const float* hd = g_h + (size_t)di * HIDD;
    const float* hm = g_h + (size_t)mi * HIDD;
    float s = 0.f;
    #pragma unroll 4
    for (int c = lane; c < HIDD; c += 32) {
        float a = hd[c], b = hm[c];
        s += a * Wp[c] + b * Wp[HIDD + c] + (a * b) * Wp[2 * HIDD + c];
    }
    #pragma unroll
    for (int o = 16; o; o >>= 1) s += __shfl_xor_sync(0xffffffffu, s, o);
    if (lane == 0) out[warp] = 1.f / (1.f + expf(-(s + bp[0])));
}

// ---------------- launch ----------------------------------------------------
extern "C" void kernel_launch(void* const* d_in, const int* in_sizes, int n_in,
                              void* d_out, int out_size)
{
    const float* d_sim    = (const float*)d_in[0];
    const float* m_sim    = (const float*)d_in[1];
    const int*   src      = (const int*)  d_in[2];
    const int*   dst      = (const int*)  d_in[3];
    const int*   diseases = (const int*)  d_in[4];
    const int*   mirnas   = (const int*)  d_in[5];
    const float* Wd       = (const float*)d_in[6];
    const float* Wm       = (const float*)d_in[7];
    const float* Wf       = (const float*)d_in[8];
    const float* bf       = (const float*)d_in[9];
    const float* Wp       = (const float*)d_in[10];
    const float* bp       = (const float*)d_in[11];
    float*       out      = (float*)d_out;

    const int E = in_sizes[2];
    const int P = in_sizes[4];

    float* feat = nullptr;  float* hbuf = nullptr;
    __nv_bfloat16 *Ahi = nullptr, *Alo = nullptr, *Bhi = nullptr, *Blo = nullptr;
    __nv_bfloat16 *Fhi = nullptr, *Flo = nullptr;
    cudaGetSymbolAddress((void**)&feat, g_feat);
    cudaGetSymbolAddress((void**)&hbuf, g_h);
    cudaGetSymbolAddress((void**)&Ahi, g_Ahi);
    cudaGetSymbolAddress((void**)&Alo, g_Alo);
    cudaGetSymbolAddress((void**)&Bhi, g_Bhi);
    cudaGetSymbolAddress((void**)&Blo, g_Blo);
    cudaGetSymbolAddress((void**)&Fhi, g_Fhi);
    cudaGetSymbolAddress((void**)&Flo, g_Flo);

    cudaFuncSetAttribute(gemm_bf16x3,
                         cudaFuncAttributeMaxDynamicSharedMemorySize, GEMM_SMEM);

    dim3 tb(32, 8);

    // ---- X_d = d_sim @ Wd -> feat[0:4096, 0:512) (+ bf16 split into Fhi/Flo)
    splitA_kernel<<<(N_D * N_D / 4 + 255) / 256, 256>>>(d_sim, Ahi, Alo, N_D * N_D / 4);
    splitBT_kernel<<<dim3(HIDD / 32, N_D / 32), tb>>>(Wd, N_D, Bhi, Blo);
    gemm_bf16x3<<<dim3(4, N_D / 128), 256, GEMM_SMEM>>>(
        Ahi, Alo, Bhi, Blo, N_D, feat, LDF, nullptr, Fhi, Flo, LDF);

    // ---- X_m = m_sim @ Wm -> feat[4096:12288, 0:512) (+ split)
    splitA_kernel<<<(N_M * N_M / 4 + 255) / 256, 256>>>(m_sim, Ahi, Alo, N_M * N_M / 4);
    splitBT_kernel<<<dim3(HIDD / 32, N_M / 32), tb>>>(Wm, N_M, Bhi, Blo);
    gemm_bf16x3<<<dim3(4, N_M / 128), 256, GEMM_SMEM>>>(      // 6th launch: profiled
        Ahi, Alo, Bhi, Blo, N_M, feat + (size_t)N_D * LDF, LDF, nullptr,
        Fhi + (size_t)N_D * LDF, Flo + (size_t)N_D * LDF, LDF);

    // ---- graph prep
    zero_kernel<<<(NN + 255) / 256, 256>>>();
    deg_kernel<<<(E + 255) / 256, 256>>>(dst, E);
    normscan_kernel<<<1, 1024>>>();
    fill_kernel<<<(E + 255) / 256, 256>>>(src, dst, E);

    // ---- K hops; each writes fp32 (except last) + bf16 split
    for (int hop = 0; hop < KHOP; hop++)
        hop_kernel<<<NN, 256>>>(hop * HIDD, (hop + 1) * HIDD, hop < KHOP - 1 ? 1 : 0);

    // ---- h = feat @ Wf + bf   (A comes pre-split from Fhi/Flo)
    splitBT_kernel<<<dim3(HIDD / 32, LDF / 32), tb>>>(Wf, LDF, Bhi, Blo);
    gemm_bf16x3<<<dim3(4, NN / 128), 256, GEMM_SMEM>>>(
        Fhi, Flo, Bhi, Blo, LDF, hbuf, HIDD, bf, nullptr, nullptr, 0);

    // ---- pair prediction with sigmoid
    pair_kernel<<<(P * 32 + 255) / 256, 256>>>(diseases, mirnas, Wp, bp, out, P);
    (void)n_in; (void)out_size;
}

// round 5
// speedup vs baseline: 4.1903x; 1.3542x over previous
#include <cuda_runtime.h>
#include <cuda_fp16.h>
#include <math.h>
#include <stdint.h>

// Problem constants (fixed shapes per reference)
#define N_D   4096
#define N_M   8192
#define NN    12288          // N_D + N_M
#define EE    196608
#define KHOP  4
#define HIDD  512
#define LDF   2560           // HID*(K+1)

// ---------------- device scratch ------------------------------------------
__device__ int   g_deg[NN];
__device__ float g_norm[NN];
__device__ int   g_offs[NN + 1];
__device__ int   g_cursor[NN];
__device__ int   g_csr_src[EE];
__device__ float g_csr_w[EE];
__device__ float g_feat[(size_t)NN * LDF];   // [N, 2560] fp32
__device__ float g_h[(size_t)NN * HIDD];     // [N, 512]  fp32
// fp16 operand buffers
__device__ __half g_Ah[(size_t)8192 * 8192]; // sim matrices, single fp16
__device__ __half g_Bhi[(size_t)512 * 8192]; // transposed weights hi
__device__ __half g_Blo[(size_t)512 * 8192]; // transposed weights lo
__device__ __half g_Fh[(size_t)NN * LDF];    // feat, single fp16

// ---------------- PTX helpers (plain sm_103-safe) ---------------------------
__device__ __forceinline__ uint32_t smem_u32(const void* p) {
    uint32_t a;
    asm("{ .reg .u64 t; cvta.to.shared.u64 t, %1; cvt.u32.u64 %0, t; }"
        : "=r"(a) : "l"(p));
    return a;
}

__device__ __forceinline__ void cpasync16(uint32_t dst, const void* src) {
    asm volatile("cp.async.cg.shared.global [%0], [%1], 16;" :: "r"(dst), "l"(src));
}
__device__ __forceinline__ void cp_commit() {
    asm volatile("cp.async.commit_group;" ::: "memory");
}
template <int N>
__device__ __forceinline__ void cp_wait() {
    asm volatile("cp.async.wait_group %0;" :: "n"(N) : "memory");
}

__device__ __forceinline__ void ldsm_x4(uint32_t addr, uint32_t& r0, uint32_t& r1,
                                        uint32_t& r2, uint32_t& r3) {
    asm volatile("ldmatrix.sync.aligned.m8n8.x4.shared.b16 {%0,%1,%2,%3}, [%4];"
                 : "=r"(r0), "=r"(r1), "=r"(r2), "=r"(r3) : "r"(addr));
}

__device__ __forceinline__ void mma16816(float* c, const uint32_t* a, const uint32_t* b) {
    asm volatile(
        "mma.sync.aligned.m16n8k16.row.col.f32.f16.f16.f32 "
        "{%0,%1,%2,%3}, {%4,%5,%6,%7}, {%8,%9}, {%0,%1,%2,%3};"
        : "+f"(c[0]), "+f"(c[1]), "+f"(c[2]), "+f"(c[3])
        : "r"(a[0]), "r"(a[1]), "r"(a[2]), "r"(a[3]), "r"(b[0]), "r"(b[1]));
}

// ---------------- graph-prep kernels ---------------------------------------
__global__ void zero_kernel() {
    int i = blockIdx.x * blockDim.x + threadIdx.x;
    if (i < NN) { g_deg[i] = 0; g_cursor[i] = 0; }
}

__global__ void deg_kernel(const int* __restrict__ dst, int E) {
    int e = blockIdx.x * blockDim.x + threadIdx.x;
    if (e < E) atomicAdd(&g_deg[dst[e]], 1);
}

// fused norm + exclusive scan (single block, warp-shuffle hierarchy)
__global__ __launch_bounds__(1024) void normscan_kernel() {
    int tid = threadIdx.x;
    int lane = tid & 31, wid = tid >> 5;
    int vals[12];
    int base = tid * 12;
    int s = 0;
    #pragma unroll
    for (int j = 0; j < 12; j++) { vals[j] = g_deg[base + j]; s += vals[j]; }
    int x = s;
    #pragma unroll
    for (int o = 1; o < 32; o <<= 1) {
        int y = __shfl_up_sync(0xffffffffu, x, o);
        if (lane >= o) x += y;
    }
    __shared__ int wsum[32];
    if (lane == 31) wsum[wid] = x;
    __syncthreads();
    if (wid == 0) {
        int w = wsum[lane];
        #pragma unroll
        for (int o = 1; o < 32; o <<= 1) {
            int y = __shfl_up_sync(0xffffffffu, w, o);
            if (lane >= o) w += y;
        }
        wsum[lane] = w;
    }
    __syncthreads();
    int run = x - s + (wid ? wsum[wid - 1] : 0);
    #pragma unroll
    for (int j = 0; j < 12; j++) { g_offs[base + j] = run; run += vals[j]; }
    if (tid == 1023) g_offs[NN] = run;
    for (int i = tid; i < NN; i += 1024) {
        int d = g_deg[i];
        g_norm[i] = rsqrtf((float)(d > 0 ? d : 1));
    }
}

__global__ void fill_kernel(const int* __restrict__ src, const int* __restrict__ dst, int E) {
    int e = blockIdx.x * blockDim.x + threadIdx.x;
    if (e < E) {
        int d = dst[e];
        int s = src[e];
        int p = g_offs[d] + atomicAdd(&g_cursor[d], 1);
        g_csr_src[p] = s;
        g_csr_w[p]   = g_norm[s] * g_norm[d];
    }
}

// ---------------- SpMM hop: gather over CSR; emits fp32 + fp16 --------------
__global__ void hop_kernel(int col_in, int col_out, int write_f32) {
    int v = blockIdx.x;
    int t = threadIdx.x;
    int s0 = g_offs[v], s1 = g_offs[v + 1];
    __shared__ int   s_src[256];
    __shared__ float s_w[256];
    float a0 = 0.f, a1 = 0.f;
    for (int base = s0; base < s1; base += 256) {
        int n = min(256, s1 - base);
        __syncthreads();
        if (t < n) { s_src[t] = g_csr_src[base + t]; s_w[t] = g_csr_w[base + t]; }
        __syncthreads();
        for (int i = 0; i < n; i++) {
            const float2* row = reinterpret_cast<const float2*>(
                g_feat + (size_t)s_src[i] * LDF + col_in);
            float w = s_w[i];
            float2 p = row[t];
            a0 += w * p.x;
            a1 += w * p.y;
        }
    }
    size_t o = (size_t)v * LDF + col_out + 2 * t;
    if (write_f32)
        *reinterpret_cast<float2*>(g_feat + o) = make_float2(a0, a1);
    *reinterpret_cast<__half2*>(g_Fh + o) = __floats2half2_rn(a0, a1);
}

// ---------------- fp32 -> fp16 convert (row-major copy) --------------------
__global__ void cvtA_kernel(const float* __restrict__ A,
                            __half* __restrict__ out, int n4)
{
    int i = blockIdx.x * blockDim.x + threadIdx.x;
    if (i >= n4) return;
    float4 v = reinterpret_cast<const float4*>(A)[i];
    uint2 p;
    __half2* hp = reinterpret_cast<__half2*>(&p);
    hp[0] = __floats2half2_rn(v.x, v.y);
    hp[1] = __floats2half2_rn(v.z, v.w);
    reinterpret_cast<uint2*>(out)[i] = p;
}

// ---------------- fp32 W[K,512] -> fp16 hi/lo transposed [512,K] -----------
__global__ void cvtBT_kernel(const float* __restrict__ W, int K,
                             __half* __restrict__ hi,
                             __half* __restrict__ lo)
{
    __shared__ float t[32][33];
    int n0 = blockIdx.x * 32;
    int k0 = blockIdx.y * 32;
    int tx = threadIdx.x, ty = threadIdx.y;  // 32 x 8
    #pragma unroll
    for (int r = 0; r < 32; r += 8)
        t[ty + r][tx] = W[(size_t)(k0 + ty + r) * HIDD + n0 + tx];
    __syncthreads();
    #pragma unroll
    for (int r = 0; r < 32; r += 8) {
        float x = t[tx][ty + r];
        __half h = __float2half_rn(x);
        __half l = __float2half_rn(x - __half2float(h));
        size_t o = (size_t)(n0 + ty + r) * K + k0 + tx;
        hi[o] = h;
        lo[o] = l;
    }
}

// ---------------- HMMA fp16x2 GEMM ------------------------------------------
// C[M,ldc](fp32) = A[M,K] @ W[K,512]; A single fp16, W split hi/lo fp16 and
// pre-transposed to [512,K]. Block tile 128x128x32, 4-stage cp.async pipeline,
// 8 warps (4Mx2N), warp tile 32x64, mma.sync m16n8k16 fp16, 2 MMAs per term.
// Optionally also writes an fp16 copy of C (for feat production).
#define GSTAGES 4
#define TILE_B   8192                 // one 128x32 fp16 tile
#define STAGE_B  (3 * TILE_B)         // A, Bhi, Blo
#define GEMM_SMEM (GSTAGES * STAGE_B) // 96 KB

__global__ __launch_bounds__(256, 1) void gemm_fp16x2(
    const __half* __restrict__ A,
    const __half* __restrict__ Bhi, const __half* __restrict__ Blo,
    int K, float* __restrict__ C, int ldc, const float* __restrict__ bias,
    __half* __restrict__ Ch, int ldc2)
{
    extern __shared__ char dynsm[];
    const uint32_t sbase = smem_u32(dynsm);

    const int tid = threadIdx.x;
    const int wid = tid >> 5;
    const int lid = tid & 31;
    const int wm  = wid >> 1;
    const int wn  = wid & 1;
    const int mbase = blockIdx.y * 128;
    const int nb0   = blockIdx.x * 128;

    const __half* gsrc[3] = {
        A + (size_t)mbase * K, Bhi + (size_t)nb0 * K, Blo + (size_t)nb0 * K };

    const int chunks = K >> 5;

    auto load_stage = [&](int stage, int c) {
        const int k0 = c << 5;
        const uint32_t sb = sbase + stage * STAGE_B;
        #pragma unroll
        for (int T = 0; T < 3; T++) {
            #pragma unroll
            for (int i = 0; i < 2; i++) {
                int idx = tid + (i << 8);
                int row = idx >> 2, ch = idx & 3;
                uint32_t sw = (uint32_t)(ch ^ ((row >> 1) & 3));
                cpasync16(sb + T * TILE_B + row * 64 + (sw << 4),
                          gsrc[T] + (size_t)row * K + k0 + ch * 8);
            }
        }
    };

    float acc[2][8][4] = {};

    #pragma unroll
    for (int s = 0; s < GSTAGES - 1; s++) { load_stage(s, s); cp_commit(); }

    for (int c = 0; c < chunks; c++) {
        cp_wait<GSTAGES - 2>();
        __syncthreads();
        const int cl = c + GSTAGES - 1;
        if (cl < chunks) load_stage(cl % GSTAGES, cl);
        cp_commit();

        const uint32_t sb = sbase + (c % GSTAGES) * STAGE_B;
        #pragma unroll
        for (int ks = 0; ks < 2; ks++) {
            uint32_t aF[2][4], bH[8][2], bL[8][2];
            #pragma unroll
            for (int mt = 0; mt < 2; mt++) {
                int row = wm * 32 + mt * 16 + (lid & 15);
                int ch  = ks * 2 + (lid >> 4);
                uint32_t off = row * 64 + ((uint32_t)(ch ^ ((row >> 1) & 3)) << 4);
                ldsm_x4(sb + off, aF[mt][0], aF[mt][1], aF[mt][2], aF[mt][3]);
            }
            #pragma unroll
            for (int nt2 = 0; nt2 < 4; nt2++) {
                int row = wn * 64 + nt2 * 16 + (lid & 7) + ((lid >> 4) << 3);
                int ch  = ks * 2 + ((lid >> 3) & 1);
                uint32_t off = row * 64 + ((uint32_t)(ch ^ ((row >> 1) & 3)) << 4);
                ldsm_x4(sb + 1 * TILE_B + off,
                        bH[2*nt2][0], bH[2*nt2][1], bH[2*nt2+1][0], bH[2*nt2+1][1]);
                ldsm_x4(sb + 2 * TILE_B + off,
                        bL[2*nt2][0], bL[2*nt2][1], bL[2*nt2+1][0], bL[2*nt2+1][1]);
            }
            #pragma unroll
            for (int mt = 0; mt < 2; mt++) {
                #pragma unroll
                for (int nt = 0; nt < 8; nt++) {
                    mma16816(acc[mt][nt], aF[mt], bH[nt]);
                    mma16816(acc[mt][nt], aF[mt], bL[nt]);
                }
            }
        }
    }

    // ---- epilogue
    const int gid = lid >> 2, tig = lid & 3;
    #pragma unroll
    for (int mt = 0; mt < 2; mt++) {
        #pragma unroll
        for (int nt = 0; nt < 8; nt++) {
            int r0  = mbase + wm * 32 + mt * 16 + gid;
            int col = nb0 + wn * 64 + nt * 8 + tig * 2;
            float2 v0 = make_float2(acc[mt][nt][0], acc[mt][nt][1]);
            float2 v1 = make_float2(acc[mt][nt][2], acc[mt][nt][3]);
            if (bias) {
                float2 bb = *reinterpret_cast<const float2*>(bias + col);
                v0.x += bb.x; v0.y += bb.y;
                v1.x += bb.x; v1.y += bb.y;
            }
            *reinterpret_cast<float2*>(C + (size_t)r0 * ldc + col)       = v0;
            *reinterpret_cast<float2*>(C + (size_t)(r0 + 8) * ldc + col) = v1;
            if (Ch) {
                *reinterpret_cast<__half2*>(Ch + (size_t)r0 * ldc2 + col) =
                    __floats2half2_rn(v0.x, v0.y);
                *reinterpret_cast<__half2*>(Ch + (size_t)(r0 + 8) * ldc2 + col) =
                    __floats2half2_rn(v1.x, v1.y);
            }
        }
    }
}

// ---------------- pair scoring: warp per pair -------------------------------
__global__ void pair_kernel(const int* __restrict__ dis, const int* __restrict__ mir,
                            const float* __restrict__ Wp, const float* __restrict__ bp,
                            float* __restrict__ out, int P)
{
    int warp = (blockIdx.x * blockDim.x + threadIdx.x) >> 5;
    int lane = threadIdx.x & 31;
    if (warp >= P) return;
    int di = dis[warp];
    int mi = mir[warp];
    const float* hd = g_h + (size_t)di * HIDD;
    const float* hm = g_h + (size_t)mi * HIDD;
    float s = 0.f;
    #pragma unroll 4
    for (int c = lane; c < HIDD; c += 32) {
        float a = hd[c], b = hm[c];
        s += a * Wp[c] + b * Wp[HIDD + c] + (a * b) * Wp[2 * HIDD + c];
    }
    #pragma unroll
    for (int o = 16; o; o >>= 1) s += __shfl_xor_sync(0xffffffffu, s, o);
    if (lane == 0) out[warp] = 1.f / (1.f + expf(-(s + bp[0])));
}

// ---------------- launch ----------------------------------------------------
extern "C" void kernel_launch(void* const* d_in, const int* in_sizes, int n_in,
                              void* d_out, int out_size)
{
    const float* d_sim    = (const float*)d_in[0];
    const float* m_sim    = (const float*)d_in[1];
    const int*   src      = (const int*)  d_in[2];
    const int*   dst      = (const int*)  d_in[3];
    const int*   diseases = (const int*)  d_in[4];
    const int*   mirnas   = (const int*)  d_in[5];
    const float* Wd       = (const float*)d_in[6];
    const float* Wm       = (const float*)d_in[7];
    const float* Wf       = (const float*)d_in[8];
    const float* bf       = (const float*)d_in[9];
    const float* Wp       = (const float*)d_in[10];
    const float* bp       = (const float*)d_in[11];
    float*       out      = (float*)d_out;

    const int E = in_sizes[2];
    const int P = in_sizes[4];

    float* feat = nullptr;  float* hbuf = nullptr;
    __half *Ah = nullptr, *Bhi = nullptr, *Blo = nullptr, *Fh = nullptr;
    cudaGetSymbolAddress((void**)&feat, g_feat);
    cudaGetSymbolAddress((void**)&hbuf, g_h);
    cudaGetSymbolAddress((void**)&Ah, g_Ah);
    cudaGetSymbolAddress((void**)&Bhi, g_Bhi);
    cudaGetSymbolAddress((void**)&Blo, g_Blo);
    cudaGetSymbolAddress((void**)&Fh, g_Fh);

    cudaFuncSetAttribute(gemm_fp16x2,
                         cudaFuncAttributeMaxDynamicSharedMemorySize, GEMM_SMEM);

    dim3 tb(32, 8);

    // ---- X_d = d_sim @ Wd -> feat[0:4096, 0:512) (+ fp16 copy into Fh)
    cvtA_kernel<<<(N_D * N_D / 4 + 255) / 256, 256>>>(d_sim, Ah, N_D * N_D / 4);
    cvtBT_kernel<<<dim3(HIDD / 32, N_D / 32), tb>>>(Wd, N_D, Bhi, Blo);
    gemm_fp16x2<<<dim3(4, N_D / 128), 256, GEMM_SMEM>>>(
        Ah, Bhi, Blo, N_D, feat, LDF, nullptr, Fh, LDF);

    // ---- X_m = m_sim @ Wm -> feat[4096:12288, 0:512) (+ fp16 copy)
    cvtA_kernel<<<(N_M * N_M / 4 + 255) / 256, 256>>>(m_sim, Ah, N_M * N_M / 4);
    cvtBT_kernel<<<dim3(HIDD / 32, N_M / 32), tb>>>(Wm, N_M, Bhi, Blo);
    gemm_fp16x2<<<dim3(4, N_M / 128), 256, GEMM_SMEM>>>(   // 6th launch: profiled
        Ah, Bhi, Blo, N_M, feat + (size_t)N_D * LDF, LDF, nullptr,
        Fh + (size_t)N_D * LDF, LDF);

    // ---- graph prep
    zero_kernel<<<(NN + 255) / 256, 256>>>();
    deg_kernel<<<(E + 255) / 256, 256>>>(dst, E);
    normscan_kernel<<<1, 1024>>>();
    fill_kernel<<<(E + 255) / 256, 256>>>(src, dst, E);

    // ---- K hops; each writes fp32 (except last) + fp16 copy
    for (int hop = 0; hop < KHOP; hop++)
        hop_kernel<<<NN, 256>>>(hop * HIDD, (hop + 1) * HIDD, hop < KHOP - 1 ? 1 : 0);

    // ---- h = feat @ Wf + bf  (A = fp16 feat from Fh)
    cvtBT_kernel<<<dim3(HIDD / 32, LDF / 32), tb>>>(Wf, LDF, Bhi, Blo);
    gemm_fp16x2<<<dim3(4, NN / 128), 256, GEMM_SMEM>>>(
        Fh, Bhi, Blo, LDF, hbuf, HIDD, bf, nullptr, 0);

    // ---- pair prediction with sigmoid
    pair_kernel<<<(P * 32 + 255) / 256, 256>>>(diseases, mirnas, Wp, bp, out, P);
    (void)n_in; (void)out_size;
}

// round 6
// speedup vs baseline: 4.2093x; 1.0045x over previous
#include <cuda_runtime.h>
#include <cuda_fp16.h>
#include <math.h>
#include <stdint.h>

// Problem constants (fixed shapes per reference)
#define N_D   4096
#define N_M   8192
#define NN    12288          // N_D + N_M
#define EE    196608
#define KHOP  4
#define HIDD  512
#define LDF   2560           // HID*(K+1)

// ---------------- device scratch ------------------------------------------
__device__ int   g_deg[NN];
__device__ float g_norm[NN];
__device__ int   g_offs[NN + 1];
__device__ int   g_cursor[NN];
__device__ int   g_csr_src[EE];
__device__ float g_csr_w[EE];
__device__ float g_h[(size_t)NN * HIDD];                 // [N, 512] fp32
__device__ __half g_Fh[(size_t)NN * LDF];                // feat, fp16
__device__ __half g_Bhi[(size_t)512 * (N_D + N_M + LDF)]; // W^T hi (d|m|f)
__device__ __half g_Blo[(size_t)512 * (N_D + N_M + LDF)]; // W^T lo

// ---------------- PTX helpers (plain sm_103-safe) ---------------------------
__device__ __forceinline__ uint32_t smem_u32(const void* p) {
    uint32_t a;
    asm("{ .reg .u64 t; cvta.to.shared.u64 t, %1; cvt.u32.u64 %0, t; }"
        : "=r"(a) : "l"(p));
    return a;
}

__device__ __forceinline__ void cpasync16(uint32_t dst, const void* src) {
    asm volatile("cp.async.cg.shared.global [%0], [%1], 16;" :: "r"(dst), "l"(src));
}
__device__ __forceinline__ void cp_commit() {
    asm volatile("cp.async.commit_group;" ::: "memory");
}
template <int N>
__device__ __forceinline__ void cp_wait() {
    asm volatile("cp.async.wait_group %0;" :: "n"(N) : "memory");
}

__device__ __forceinline__ void ldsm_x4(uint32_t addr, uint32_t& r0, uint32_t& r1,
                                        uint32_t& r2, uint32_t& r3) {
    asm volatile("ldmatrix.sync.aligned.m8n8.x4.shared.b16 {%0,%1,%2,%3}, [%4];"
                 : "=r"(r0), "=r"(r1), "=r"(r2), "=r"(r3) : "r"(addr));
}

__device__ __forceinline__ void mma16816(float* c, const uint32_t* a, const uint32_t* b) {
    asm volatile(
        "mma.sync.aligned.m16n8k16.row.col.f32.f16.f16.f32 "
        "{%0,%1,%2,%3}, {%4,%5,%6,%7}, {%8,%9}, {%0,%1,%2,%3};"
        : "+f"(c[0]), "+f"(c[1]), "+f"(c[2]), "+f"(c[3])
        : "r"(a[0]), "r"(a[1]), "r"(a[2]), "r"(a[3]), "r"(b[0]), "r"(b[1]));
}

__device__ __forceinline__ uint32_t pack2(float a, float b) {
    __half2 h = __floats2half2_rn(a, b);
    return *reinterpret_cast<uint32_t*>(&h);
}

// ---------------- graph-prep kernels ---------------------------------------
__global__ void zero_kernel() {
    int i = blockIdx.x * blockDim.x + threadIdx.x;
    if (i < NN) { g_deg[i] = 0; g_cursor[i] = 0; }
}

__global__ void deg_kernel(const int* __restrict__ dst, int E) {
    int e = blockIdx.x * blockDim.x + threadIdx.x;
    if (e < E) atomicAdd(&g_deg[dst[e]], 1);
}

// fused norm + exclusive scan (single block, warp-shuffle hierarchy)
__global__ __launch_bounds__(1024) void normscan_kernel() {
    int tid = threadIdx.x;
    int lane = tid & 31, wid = tid >> 5;
    int vals[12];
    int base = tid * 12;
    int s = 0;
    #pragma unroll
    for (int j = 0; j < 12; j++) { vals[j] = g_deg[base + j]; s += vals[j]; }
    int x = s;
    #pragma unroll
    for (int o = 1; o < 32; o <<= 1) {
        int y = __shfl_up_sync(0xffffffffu, x, o);
        if (lane >= o) x += y;
    }
    __shared__ int wsum[32];
    if (lane == 31) wsum[wid] = x;
    __syncthreads();
    if (wid == 0) {
        int w = wsum[lane];
        #pragma unroll
        for (int o = 1; o < 32; o <<= 1) {
            int y = __shfl_up_sync(0xffffffffu, w, o);
            if (lane >= o) w += y;
        }
        wsum[lane] = w;
    }
    __syncthreads();
    int run = x - s + (wid ? wsum[wid - 1] : 0);
    #pragma unroll
    for (int j = 0; j < 12; j++) { g_offs[base + j] = run; run += vals[j]; }
    if (tid == 1023) g_offs[NN] = run;
    for (int i = tid; i < NN; i += 1024) {
        int d = g_deg[i];
        g_norm[i] = rsqrtf((float)(d > 0 ? d : 1));
    }
}

__global__ void fill_kernel(const int* __restrict__ src, const int* __restrict__ dst, int E) {
    int e = blockIdx.x * blockDim.x + threadIdx.x;
    if (e < E) {
        int d = dst[e];
        int s = src[e];
        int p = g_offs[d] + atomicAdd(&g_cursor[d], 1);
        g_csr_src[p] = s;
        g_csr_w[p]   = g_norm[s] * g_norm[d];
    }
}

// ---------------- SpMM hop: fp16 gather over CSR, fp32 accumulate ----------
__global__ void hop_kernel(int col_in, int col_out) {
    int v = blockIdx.x;
    int t = threadIdx.x;
    int s0 = g_offs[v], s1 = g_offs[v + 1];
    __shared__ int   s_src[256];
    __shared__ float s_w[256];
    float a0 = 0.f, a1 = 0.f;
    for (int base = s0; base < s1; base += 256) {
        int n = min(256, s1 - base);
        __syncthreads();
        if (t < n) { s_src[t] = g_csr_src[base + t]; s_w[t] = g_csr_w[base + t]; }
        __syncthreads();
        for (int i = 0; i < n; i++) {
            const __half2* row = reinterpret_cast<const __half2*>(
                g_Fh + (size_t)s_src[i] * LDF + col_in);
            float w = s_w[i];
            float2 p = __half22float2(row[t]);
            a0 += w * p.x;
            a1 += w * p.y;
        }
    }
    *reinterpret_cast<__half2*>(g_Fh + (size_t)v * LDF + col_out + 2 * t) =
        __floats2half2_rn(a0, a1);
}

// ---------------- fused weight transpose+split: Wd|Wm|Wf -> [512,K] hi/lo ---
__global__ void cvtBT_all(const float* __restrict__ Wd, const float* __restrict__ Wm,
                          const float* __restrict__ Wf,
                          __half* __restrict__ hi, __half* __restrict__ lo)
{
    const float* W; int K; size_t offs;
    int z = blockIdx.z;
    if (z == 0)      { W = Wd; K = N_D; offs = 0; }
    else if (z == 1) { W = Wm; K = N_M; offs = (size_t)512 * N_D; }
    else             { W = Wf; K = LDF; offs = (size_t)512 * (N_D + N_M); }
    int k0 = blockIdx.y * 32;
    if (k0 >= K) return;

    __shared__ float t[32][33];
    int n0 = blockIdx.x * 32;
    int tx = threadIdx.x, ty = threadIdx.y;  // 32 x 8
    #pragma unroll
    for (int r = 0; r < 32; r += 8)
        t[ty + r][tx] = W[(size_t)(k0 + ty + r) * HIDD + n0 + tx];
    __syncthreads();
    #pragma unroll
    for (int r = 0; r < 32; r += 8) {
        float x = t[tx][ty + r];
        __half h = __float2half_rn(x);
        __half l = __float2half_rn(x - __half2float(h));
        size_t o = offs + (size_t)(n0 + ty + r) * K + k0 + tx;
        hi[o] = h;
        lo[o] = l;
    }
}

// ---------------- shared GEMM core parameters ------------------------------
#define GSTAGES 4
#define TILE_B   8192                 // one 128x32 fp16 tile
#define STAGE_B  (3 * TILE_B)         // A, Bhi, Blo
#define GEMM_SMEM (GSTAGES * STAGE_B) // 96 KB

// ---------------- gemm_dm: fused d+m feature GEMMs --------------------------
// Fh[r,0:512) = sim @ W, A fp32 loaded directly (register-staged fp16 cvt),
// W split hi/lo fp16 pre-transposed. Tiles: by<64 -> m_sim, else d_sim.
__global__ __launch_bounds__(256, 1) void gemm_dm(
    const float* __restrict__ Ad, const float* __restrict__ Am,
    const __half* __restrict__ Bhi, const __half* __restrict__ Blo)
{
    extern __shared__ char dynsm[];
    const uint32_t sbase = smem_u32(dynsm);

    const int tid = threadIdx.x;
    const int wid = tid >> 5;
    const int lid = tid & 31;
    const int wm  = wid >> 1;
    const int wn  = wid & 1;
    const int by  = blockIdx.y;
    const int nb0 = blockIdx.x * 128;

    const float* A; int K; int crow;
    const __half *bh, *bl;
    if (by < 64) {   // m tiles first (longer) for better tail packing
        A = Am + (size_t)by * 128 * N_M; K = N_M; crow = N_D + by * 128;
        bh = Bhi + (size_t)512 * N_D; bl = Blo + (size_t)512 * N_D;
    } else {
        A = Ad + (size_t)(by - 64) * 128 * N_D; K = N_D; crow = (by - 64) * 128;
        bh = Bhi; bl = Blo;
    }
    const __half* Bh = bh + (size_t)nb0 * K;
    const __half* Bl = bl + (size_t)nb0 * K;
    const int chunks = K >> 5;

    const int arow = tid >> 1, ahalf = tid & 1;
    const float* arp = A + (size_t)arow * K + ahalf * 16;

    auto ldgA = [&](int c, float4* av) {
        const float4* p = reinterpret_cast<const float4*>(arp + (c << 5));
        av[0] = p[0]; av[1] = p[1]; av[2] = p[2]; av[3] = p[3];
    };
    auto stsA = [&](int stage, const float4* av) {
        uint4 u0, u1;
        u0.x = pack2(av[0].x, av[0].y); u0.y = pack2(av[0].z, av[0].w);
        u0.z = pack2(av[1].x, av[1].y); u0.w = pack2(av[1].z, av[1].w);
        u1.x = pack2(av[2].x, av[2].y); u1.y = pack2(av[2].z, av[2].w);
        u1.z = pack2(av[3].x, av[3].y); u1.w = pack2(av[3].z, av[3].w);
        char* p = dynsm + stage * STAGE_B + arow * 64;
        int ch0 = ahalf * 2;
        int sw  = (arow >> 1) & 3;
        *reinterpret_cast<uint4*>(p + ((ch0 ^ sw) << 4))       = u0;
        *reinterpret_cast<uint4*>(p + (((ch0 + 1) ^ sw) << 4)) = u1;
    };
    auto loadB = [&](int stage, int c) {
        const int k0 = c << 5;
        const uint32_t sb = sbase + stage * STAGE_B;
        #pragma unroll
        for (int T = 0; T < 2; T++) {
            const __half* g = T ? Bl : Bh;
            #pragma unroll
            for (int i = 0; i < 2; i++) {
                int idx = tid + (i << 8);
                int row = idx >> 2, ch = idx & 3;
                uint32_t sw = (uint32_t)(ch ^ ((row >> 1) & 3));
                cpasync16(sb + (T + 1) * TILE_B + row * 64 + (sw << 4),
                          g + (size_t)row * K + k0 + ch * 8);
            }
        }
    };

    float acc[2][8][4] = {};

    #pragma unroll
    for (int s = 0; s < GSTAGES - 1; s++) {
        float4 av[4];
        ldgA(s, av);
        stsA(s, av);
        loadB(s, s);
        cp_commit();
    }

    for (int c = 0; c < chunks; c++) {
        cp_wait<GSTAGES - 2>();
        __syncthreads();
        const int cl = c + GSTAGES - 1;
        const bool dold = (cl < chunks);
        float4 av[4];
        if (dold) { ldgA(cl, av); loadB(cl % GSTAGES, cl); }
        cp_commit();

        const uint32_t sb = sbase + (c % GSTAGES) * STAGE_B;
        #pragma unroll
        for (int ks = 0; ks < 2; ks++) {
            uint32_t aF[2][4], bH[8][2], bL[8][2];
            #pragma unroll
            for (int mt = 0; mt < 2; mt++) {
                int row = wm * 32 + mt * 16 + (lid & 15);
                int ch  = ks * 2 + (lid >> 4);
                uint32_t off = row * 64 + ((uint32_t)(ch ^ ((row >> 1) & 3)) << 4);
                ldsm_x4(sb + off, aF[mt][0], aF[mt][1], aF[mt][2], aF[mt][3]);
            }
            #pragma unroll
            for (int nt2 = 0; nt2 < 4; nt2++) {
                int row = wn * 64 + nt2 * 16 + (lid & 7) + ((lid >> 4) << 3);
                int ch  = ks * 2 + ((lid >> 3) & 1);
                uint32_t off = row * 64 + ((uint32_t)(ch ^ ((row >> 1) & 3)) << 4);
                ldsm_x4(sb + 1 * TILE_B + off,
                        bH[2*nt2][0], bH[2*nt2][1], bH[2*nt2+1][0], bH[2*nt2+1][1]);
                ldsm_x4(sb + 2 * TILE_B + off,
                        bL[2*nt2][0], bL[2*nt2][1], bL[2*nt2+1][0], bL[2*nt2+1][1]);
            }
            #pragma unroll
            for (int mt = 0; mt < 2; mt++) {
                #pragma unroll
                for (int nt = 0; nt < 8; nt++) {
                    mma16816(acc[mt][nt], aF[mt], bH[nt]);
                    mma16816(acc[mt][nt], aF[mt], bL[nt]);
                }
            }
        }
        if (dold) stsA(cl % GSTAGES, av);
    }

    // ---- epilogue: write fp16 feat only
    const int gid = lid >> 2, tig = lid & 3;
    #pragma unroll
    for (int mt = 0; mt < 2; mt++) {
        #pragma unroll
        for (int nt = 0; nt < 8; nt++) {
            int r0  = crow + wm * 32 + mt * 16 + gid;
            int col = nb0 + wn * 64 + nt * 8 + tig * 2;
            *reinterpret_cast<__half2*>(g_Fh + (size_t)r0 * LDF + col) =
                __floats2half2_rn(acc[mt][nt][0], acc[mt][nt][1]);
            *reinterpret_cast<__half2*>(g_Fh + (size_t)(r0 + 8) * LDF + col) =
                __floats2half2_rn(acc[mt][nt][2], acc[mt][nt][3]);
        }
    }
}

// ---------------- gemm_f: h = feat(fp16) @ Wf + bf --------------------------
__global__ __launch_bounds__(256, 1) void gemm_f(
    const __half* __restrict__ A,
    const __half* __restrict__ Bhi, const __half* __restrict__ Blo,
    int K, float* __restrict__ C, int ldc, const float* __restrict__ bias)
{
    extern __shared__ char dynsm[];
    const uint32_t sbase = smem_u32(dynsm);

    const int tid = threadIdx.x;
    const int wid = tid >> 5;
    const int lid = tid & 31;
    const int wm  = wid >> 1;
    const int wn  = wid & 1;
    const int mbase = blockIdx.y * 128;
    const int nb0   = blockIdx.x * 128;

    const __half* gsrc[3] = {
        A + (size_t)mbase * K, Bhi + (size_t)nb0 * K, Blo + (size_t)nb0 * K };

    const int chunks = K >> 5;

    auto load_stage = [&](int stage, int c) {
        const int k0 = c << 5;
        const uint32_t sb = sbase + stage * STAGE_B;
        #pragma unroll
        for (int T = 0; T < 3; T++) {
            #pragma unroll
            for (int i = 0; i < 2; i++) {
                int idx = tid + (i << 8);
                int row = idx >> 2, ch = idx & 3;
                uint32_t sw = (uint32_t)(ch ^ ((row >> 1) & 3));
                cpasync16(sb + T * TILE_B + row * 64 + (sw << 4),
                          gsrc[T] + (size_t)row * K + k0 + ch * 8);
            }
        }
    };

    float acc[2][8][4] = {};

    #pragma unroll
    for (int s = 0; s < GSTAGES - 1; s++) { load_stage(s, s); cp_commit(); }

    for (int c = 0; c < chunks; c++) {
        cp_wait<GSTAGES - 2>();
        __syncthreads();
        const int cl = c + GSTAGES - 1;
        if (cl < chunks) load_stage(cl % GSTAGES, cl);
        cp_commit();

        const uint32_t sb = sbase + (c % GSTAGES) * STAGE_B;
        #pragma unroll
        for (int ks = 0; ks < 2; ks++) {
            uint32_t aF[2][4], bH[8][2], bL[8][2];
            #pragma unroll
            for (int mt = 0; mt < 2; mt++) {
                int row = wm * 32 + mt * 16 + (lid & 15);
                int ch  = ks * 2 + (lid >> 4);
                uint32_t off = row * 64 + ((uint32_t)(ch ^ ((row >> 1) & 3)) << 4);
                ldsm_x4(sb + off, aF[mt][0], aF[mt][1], aF[mt][2], aF[mt][3]);
            }
            #pragma unroll
            for (int nt2 = 0; nt2 < 4; nt2++) {
                int row = wn * 64 + nt2 * 16 + (lid & 7) + ((lid >> 4) << 3);
                int ch  = ks * 2 + ((lid >> 3) & 1);
                uint32_t off = row * 64 + ((uint32_t)(ch ^ ((row >> 1) & 3)) << 4);
                ldsm_x4(sb + 1 * TILE_B + off,
                        bH[2*nt2][0], bH[2*nt2][1], bH[2*nt2+1][0], bH[2*nt2+1][1]);
                ldsm_x4(sb + 2 * TILE_B + off,
                        bL[2*nt2][0], bL[2*nt2][1], bL[2*nt2+1][0], bL[2*nt2+1][1]);
            }
            #pragma unroll
            for (int mt = 0; mt < 2; mt++) {
                #pragma unroll
                for (int nt = 0; nt < 8; nt++) {
                    mma16816(acc[mt][nt], aF[mt], bH[nt]);
                    mma16816(acc[mt][nt], aF[mt], bL[nt]);
                }
            }
        }
    }

    const int gid = lid >> 2, tig = lid & 3;
    #pragma unroll
    for (int mt = 0; mt < 2; mt++) {
        #pragma unroll
        for (int nt = 0; nt < 8; nt++) {
            int r0  = mbase + wm * 32 + mt * 16 + gid;
            int col = nb0 + wn * 64 + nt * 8 + tig * 2;
            float2 bb = *reinterpret_cast<const float2*>(bias + col);
            float2 v0 = make_float2(acc[mt][nt][0] + bb.x, acc[mt][nt][1] + bb.y);
            float2 v1 = make_float2(acc[mt][nt][2] + bb.x, acc[mt][nt][3] + bb.y);
            *reinterpret_cast<float2*>(C + (size_t)r0 * ldc + col)       = v0;
            *reinterpret_cast<float2*>(C + (size_t)(r0 + 8) * ldc + col) = v1;
        }
    }
}

// ---------------- pair scoring: warp per pair -------------------------------
__global__ void pair_kernel(const int* __restrict__ dis, const int* __restrict__ mir,
                            const float* __restrict__ Wp, const float* __restrict__ bp,
                            float* __restrict__ out, int P)
{
    int warp = (blockIdx.x * blockDim.x + threadIdx.x) >> 5;
    int lane = threadIdx.x & 31;
    if (warp >= P) return;
    int di = dis[warp];
    int mi = mir[warp];
    const float* hd = g_h + (size_t)di * HIDD;
    const float* hm = g_h + (size_t)mi * HIDD;
    float s = 0.f;
    #pragma unroll 4
    for (int c = lane; c < HIDD; c += 32) {
        float a = hd[c], b = hm[c];
        s += a * Wp[c] + b * Wp[HIDD + c] + (a * b) * Wp[2 * HIDD + c];
    }
    #pragma unroll
    for (int o = 16; o; o >>= 1) s += __shfl_xor_sync(0xffffffffu, s, o);
    if (lane == 0) out[warp] = 1.f / (1.f + expf(-(s + bp[0])));
}

// ---------------- launch ----------------------------------------------------
extern "C" void kernel_launch(void* const* d_in, const int* in_sizes, int n_in,
                              void* d_out, int out_size)
{
    const float* d_sim    = (const float*)d_in[0];
    const float* m_sim    = (const float*)d_in[1];
    const int*   src      = (const int*)  d_in[2];
    const int*   dst      = (const int*)  d_in[3];
    const int*   diseases = (const int*)  d_in[4];
    const int*   mirnas   = (const int*)  d_in[5];
    const float* Wd       = (const float*)d_in[6];
    const float* Wm       = (const float*)d_in[7];
    const float* Wf       = (const float*)d_in[8];
    const float* bf       = (const float*)d_in[9];
    const float* Wp       = (const float*)d_in[10];
    const float* bp       = (const float*)d_in[11];
    float*       out      = (float*)d_out;

    const int E = in_sizes[2];
    const int P = in_sizes[4];

    float* hbuf = nullptr;
    __half *Bhi = nullptr, *Blo = nullptr, *Fh = nullptr;
    cudaGetSymbolAddress((void**)&hbuf, g_h);
    cudaGetSymbolAddress((void**)&Bhi, g_Bhi);
    cudaGetSymbolAddress((void**)&Blo, g_Blo);
    cudaGetSymbolAddress((void**)&Fh, g_Fh);

    cudaFuncSetAttribute(gemm_dm, cudaFuncAttributeMaxDynamicSharedMemorySize, GEMM_SMEM);
    cudaFuncSetAttribute(gemm_f,  cudaFuncAttributeMaxDynamicSharedMemorySize, GEMM_SMEM);

    // ---- graph prep (launches 1-4)
    zero_kernel<<<(NN + 255) / 256, 256>>>();
    deg_kernel<<<(E + 255) / 256, 256>>>(dst, E);
    normscan_kernel<<<1, 1024>>>();
    fill_kernel<<<(E + 255) / 256, 256>>>(src, dst, E);

    // ---- all weight transposes in one launch (5)
    cvtBT_all<<<dim3(HIDD / 32, N_M / 32, 3), dim3(32, 8)>>>(Wd, Wm, Wf, Bhi, Blo);

    // ---- fused d+m feature GEMM -> Fh[:, 0:512)  (6th launch: profiled)
    gemm_dm<<<dim3(4, 96), 256, GEMM_SMEM>>>(d_sim, m_sim, Bhi, Blo);

    // ---- K hops of normalized gather-sum (fp16 feat, fp32 accumulate)
    for (int hop = 0; hop < KHOP; hop++)
        hop_kernel<<<NN, 256>>>(hop * HIDD, (hop + 1) * HIDD);

    // ---- h = feat @ Wf + bf
    gemm_f<<<dim3(4, 96), 256, GEMM_SMEM>>>(
        Fh, Bhi + (size_t)512 * (N_D + N_M), Blo + (size_t)512 * (N_D + N_M),
        LDF, hbuf, HIDD, bf);

    // ---- pair prediction with sigmoid
    pair_kernel<<<(P * 32 + 255) / 256, 256>>>(diseases, mirnas, Wp, bp, out, P);
    (void)n_in; (void)out_size;
}

// round 7
// speedup vs baseline: 4.7001x; 1.1166x over previous
#include <cuda_runtime.h>
#include <cuda_fp16.h>
#include <math.h>
#include <stdint.h>

// Problem constants (fixed shapes per reference)
#define N_D   4096
#define N_M   8192
#define NN    12288          // N_D + N_M
#define EE    196608
#define KHOP  4
#define HIDD  512
#define LDF   2560           // HID*(K+1)

// ---------------- device scratch ------------------------------------------
__device__ int   g_deg[NN];
__device__ float g_norm[NN];
__device__ int   g_offs[NN + 1];
__device__ int   g_cursor[NN];
__device__ int   g_csr_src[EE];
__device__ float g_csr_w[EE];
__device__ float g_h[(size_t)NN * HIDD];                  // [N, 512] fp32
__device__ __half g_Fh[(size_t)NN * LDF];                 // feat, fp16
__device__ __half g_Bt[(size_t)512 * (N_D + N_M + LDF)];  // W^T fp16 (d|m|f)

// ---------------- PTX helpers (plain sm_103-safe) ---------------------------
__device__ __forceinline__ uint32_t smem_u32(const void* p) {
    uint32_t a;
    asm("{ .reg .u64 t; cvta.to.shared.u64 t, %1; cvt.u32.u64 %0, t; }"
        : "=r"(a) : "l"(p));
    return a;
}

__device__ __forceinline__ void cpasync16(uint32_t dst, const void* src) {
    asm volatile("cp.async.cg.shared.global [%0], [%1], 16;" :: "r"(dst), "l"(src));
}
__device__ __forceinline__ void cp_commit() {
    asm volatile("cp.async.commit_group;" ::: "memory");
}
template <int N>
__device__ __forceinline__ void cp_wait() {
    asm volatile("cp.async.wait_group %0;" :: "n"(N) : "memory");
}

__device__ __forceinline__ void ldsm_x4(uint32_t addr, uint32_t& r0, uint32_t& r1,
                                        uint32_t& r2, uint32_t& r3) {
    asm volatile("ldmatrix.sync.aligned.m8n8.x4.shared.b16 {%0,%1,%2,%3}, [%4];"
                 : "=r"(r0), "=r"(r1), "=r"(r2), "=r"(r3) : "r"(addr));
}

__device__ __forceinline__ void mma16816(float* c, const uint32_t* a, const uint32_t* b) {
    asm volatile(
        "mma.sync.aligned.m16n8k16.row.col.f32.f16.f16.f32 "
        "{%0,%1,%2,%3}, {%4,%5,%6,%7}, {%8,%9}, {%0,%1,%2,%3};"
        : "+f"(c[0]), "+f"(c[1]), "+f"(c[2]), "+f"(c[3])
        : "r"(a[0]), "r"(a[1]), "r"(a[2]), "r"(a[3]), "r"(b[0]), "r"(b[1]));
}

__device__ __forceinline__ uint32_t pack2(float a, float b) {
    __half2 h = __floats2half2_rn(a, b);
    return *reinterpret_cast<uint32_t*>(&h);
}

// ---------------- graph-prep kernels ---------------------------------------
__global__ void zero_kernel() {
    int i = blockIdx.x * blockDim.x + threadIdx.x;
    if (i < NN) { g_deg[i] = 0; g_cursor[i] = 0; }
}

__global__ void deg_kernel(const int* __restrict__ dst, int E) {
    int e = blockIdx.x * blockDim.x + threadIdx.x;
    if (e < E) atomicAdd(&g_deg[dst[e]], 1);
}

// fused norm + exclusive scan (single block, warp-shuffle hierarchy)
__global__ __launch_bounds__(1024) void normscan_kernel() {
    int tid = threadIdx.x;
    int lane = tid & 31, wid = tid >> 5;
    int vals[12];
    int base = tid * 12;
    int s = 0;
    #pragma unroll
    for (int j = 0; j < 12; j++) { vals[j] = g_deg[base + j]; s += vals[j]; }
    int x = s;
    #pragma unroll
    for (int o = 1; o < 32; o <<= 1) {
        int y = __shfl_up_sync(0xffffffffu, x, o);
        if (lane >= o) x += y;
    }
    __shared__ int wsum[32];
    if (lane == 31) wsum[wid] = x;
    __syncthreads();
    if (wid == 0) {
        int w = wsum[lane];
        #pragma unroll
        for (int o = 1; o < 32; o <<= 1) {
            int y = __shfl_up_sync(0xffffffffu, w, o);
            if (lane >= o) w += y;
        }
        wsum[lane] = w;
    }
    __syncthreads();
    int run = x - s + (wid ? wsum[wid - 1] : 0);
    #pragma unroll
    for (int j = 0; j < 12; j++) { g_offs[base + j] = run; run += vals[j]; }
    if (tid == 1023) g_offs[NN] = run;
    for (int i = tid; i < NN; i += 1024) {
        int d = g_deg[i];
        g_norm[i] = rsqrtf((float)(d > 0 ? d : 1));
    }
}

__global__ void fill_kernel(const int* __restrict__ src, const int* __restrict__ dst, int E) {
    int e = blockIdx.x * blockDim.x + threadIdx.x;
    if (e < E) {
        int d = dst[e];
        int s = src[e];
        int p = g_offs[d] + atomicAdd(&g_cursor[d], 1);
        g_csr_src[p] = s;
        g_csr_w[p]   = g_norm[s] * g_norm[d];
    }
}

// ---------------- SpMM hop: fp16 gather over CSR, fp32 accumulate ----------
__global__ void hop_kernel(int col_in, int col_out) {
    int v = blockIdx.x;
    int t = threadIdx.x;
    int s0 = g_offs[v], s1 = g_offs[v + 1];
    __shared__ int   s_src[256];
    __shared__ float s_w[256];
    float a0 = 0.f, a1 = 0.f;
    for (int base = s0; base < s1; base += 256) {
        int n = min(256, s1 - base);
        __syncthreads();
        if (t < n) { s_src[t] = g_csr_src[base + t]; s_w[t] = g_csr_w[base + t]; }
        __syncthreads();
        for (int i = 0; i < n; i++) {
            const __half2* row = reinterpret_cast<const __half2*>(
                g_Fh + (size_t)s_src[i] * LDF + col_in);
            float w = s_w[i];
            float2 p = __half22float2(row[t]);
            a0 += w * p.x;
            a1 += w * p.y;
        }
    }
    *reinterpret_cast<__half2*>(g_Fh + (size_t)v * LDF + col_out + 2 * t) =
        __floats2half2_rn(a0, a1);
}

// ---------------- fused weight transpose: Wd|Wm|Wf -> [512,K] fp16 ----------
__global__ void cvtBT_all(const float* __restrict__ Wd, const float* __restrict__ Wm,
                          const float* __restrict__ Wf, __half* __restrict__ o)
{
    const float* W; int K; size_t offs;
    int z = blockIdx.z;
    if (z == 0)      { W = Wd; K = N_D; offs = 0; }
    else if (z == 1) { W = Wm; K = N_M; offs = (size_t)512 * N_D; }
    else             { W = Wf; K = LDF; offs = (size_t)512 * (N_D + N_M); }
    int k0 = blockIdx.y * 32;
    if (k0 >= K) return;

    __shared__ float t[32][33];
    int n0 = blockIdx.x * 32;
    int tx = threadIdx.x, ty = threadIdx.y;  // 32 x 8
    #pragma unroll
    for (int r = 0; r < 32; r += 8)
        t[ty + r][tx] = W[(size_t)(k0 + ty + r) * HIDD + n0 + tx];
    __syncthreads();
    #pragma unroll
    for (int r = 0; r < 32; r += 8)
        o[offs + (size_t)(n0 + ty + r) * K + k0 + tx] = __float2half_rn(t[tx][ty + r]);
}

// ---------------- shared GEMM core parameters ------------------------------
#define GSTAGES 4
#define TILE_B   8192                 // one 128x32 fp16 tile
#define STAGE_B  (2 * TILE_B)         // A, B
#define GEMM_SMEM (GSTAGES * STAGE_B) // 64 KB

// ---------------- gemm_dm: fused d+m feature GEMMs --------------------------
// Fh[r,0:512) = sim @ W; A fp32 loaded directly (register-staged fp16 cvt),
// W fp16 pre-transposed. Tiles: by<64 -> m_sim, else d_sim.
__global__ __launch_bounds__(256, 1) void gemm_dm(
    const float* __restrict__ Ad, const float* __restrict__ Am,
    const __half* __restrict__ Bt)
{
    extern __shared__ char dynsm[];
    const uint32_t sbase = smem_u32(dynsm);

    const int tid = threadIdx.x;
    const int wid = tid >> 5;
    const int lid = tid & 31;
    const int wm  = wid >> 1;
    const int wn  = wid & 1;
    const int by  = blockIdx.y;
    const int nb0 = blockIdx.x * 128;

    const float* A; int K; int crow;
    const __half* bh;
    if (by < 64) {   // m tiles first (longer) for better tail packing
        A = Am + (size_t)by * 128 * N_M; K = N_M; crow = N_D + by * 128;
        bh = Bt + (size_t)512 * N_D;
    } else {
        A = Ad + (size_t)(by - 64) * 128 * N_D; K = N_D; crow = (by - 64) * 128;
        bh = Bt;
    }
    const __half* Bh = bh + (size_t)nb0 * K;
    const int chunks = K >> 5;

    const int arow = tid >> 1, ahalf = tid & 1;
    const float* arp = A + (size_t)arow * K + ahalf * 16;

    auto ldgA = [&](int c, float4* av) {
        const float4* p = reinterpret_cast<const float4*>(arp + (c << 5));
        av[0] = p[0]; av[1] = p[1]; av[2] = p[2]; av[3] = p[3];
    };
    auto stsA = [&](int stage, const float4* av) {
        uint4 u0, u1;
        u0.x = pack2(av[0].x, av[0].y); u0.y = pack2(av[0].z, av[0].w);
        u0.z = pack2(av[1].x, av[1].y); u0.w = pack2(av[1].z, av[1].w);
        u1.x = pack2(av[2].x, av[2].y); u1.y = pack2(av[2].z, av[2].w);
        u1.z = pack2(av[3].x, av[3].y); u1.w = pack2(av[3].z, av[3].w);
        char* p = dynsm + stage * STAGE_B + arow * 64;
        int ch0 = ahalf * 2;
        int sw  = (arow >> 1) & 3;
        *reinterpret_cast<uint4*>(p + ((ch0 ^ sw) << 4))       = u0;
        *reinterpret_cast<uint4*>(p + (((ch0 + 1) ^ sw) << 4)) = u1;
    };
    auto loadB = [&](int stage, int c) {
        const int k0 = c << 5;
        const uint32_t sb = sbase + stage * STAGE_B;
        #pragma unroll
        for (int i = 0; i < 2; i++) {
            int idx = tid + (i << 8);
            int row = idx >> 2, ch = idx & 3;
            uint32_t sw = (uint32_t)(ch ^ ((row >> 1) & 3));
            cpasync16(sb + TILE_B + row * 64 + (sw << 4),
                      Bh + (size_t)row * K + k0 + ch * 8);
        }
    };

    float acc[2][8][4] = {};

    #pragma unroll
    for (int s = 0; s < GSTAGES - 1; s++) {
        float4 av[4];
        ldgA(s, av);
        stsA(s, av);
        loadB(s, s);
        cp_commit();
    }

    for (int c = 0; c < chunks; c++) {
        cp_wait<GSTAGES - 2>();
        __syncthreads();
        const int cl = c + GSTAGES - 1;
        const bool dold = (cl < chunks);
        float4 av[4];
        if (dold) { ldgA(cl, av); loadB(cl % GSTAGES, cl); }
        cp_commit();

        const uint32_t sb = sbase + (c % GSTAGES) * STAGE_B;
        #pragma unroll
        for (int ks = 0; ks < 2; ks++) {
            uint32_t aF[2][4], bF[8][2];
            #pragma unroll
            for (int mt = 0; mt < 2; mt++) {
                int row = wm * 32 + mt * 16 + (lid & 15);
                int ch  = ks * 2 + (lid >> 4);
                uint32_t off = row * 64 + ((uint32_t)(ch ^ ((row >> 1) & 3)) << 4);
                ldsm_x4(sb + off, aF[mt][0], aF[mt][1], aF[mt][2], aF[mt][3]);
            }
            #pragma unroll
            for (int nt2 = 0; nt2 < 4; nt2++) {
                int row = wn * 64 + nt2 * 16 + (lid & 7) + ((lid >> 4) << 3);
                int ch  = ks * 2 + ((lid >> 3) & 1);
                uint32_t off = row * 64 + ((uint32_t)(ch ^ ((row >> 1) & 3)) << 4);
                ldsm_x4(sb + TILE_B + off,
                        bF[2*nt2][0], bF[2*nt2][1], bF[2*nt2+1][0], bF[2*nt2+1][1]);
            }
            #pragma unroll
            for (int mt = 0; mt < 2; mt++)
                #pragma unroll
                for (int nt = 0; nt < 8; nt++)
                    mma16816(acc[mt][nt], aF[mt], bF[nt]);
        }
        if (dold) stsA(cl % GSTAGES, av);
    }

    // ---- epilogue: write fp16 feat only
    const int gid = lid >> 2, tig = lid & 3;
    #pragma unroll
    for (int mt = 0; mt < 2; mt++) {
        #pragma unroll
        for (int nt = 0; nt < 8; nt++) {
            int r0  = crow + wm * 32 + mt * 16 + gid;
            int col = nb0 + wn * 64 + nt * 8 + tig * 2;
            *reinterpret_cast<__half2*>(g_Fh + (size_t)r0 * LDF + col) =
                __floats2half2_rn(acc[mt][nt][0], acc[mt][nt][1]);
            *reinterpret_cast<__half2*>(g_Fh + (size_t)(r0 + 8) * LDF + col) =
                __floats2half2_rn(acc[mt][nt][2], acc[mt][nt][3]);
        }
    }
}

// ---------------- gemm_f: h = feat(fp16) @ Wf + bf --------------------------
__global__ __launch_bounds__(256, 1) void gemm_f(
    const __half* __restrict__ A, const __half* __restrict__ Bt,
    int K, float* __restrict__ C, int ldc, const float* __restrict__ bias)
{
    extern __shared__ char dynsm[];
    const uint32_t sbase = smem_u32(dynsm);

    const int tid = threadIdx.x;
    const int wid = tid >> 5;
    const int lid = tid & 31;
    const int wm  = wid >> 1;
    const int wn  = wid & 1;
    const int mbase = blockIdx.y * 128;
    const int nb0   = blockIdx.x * 128;

    const __half* gsrc[2] = { A + (size_t)mbase * K, Bt + (size_t)nb0 * K };
    const int chunks = K >> 5;

    auto load_stage = [&](int stage, int c) {
        const int k0 = c << 5;
        const uint32_t sb = sbase + stage * STAGE_B;
        #pragma unroll
        for (int T = 0; T < 2; T++) {
            #pragma unroll
            for (int i = 0; i < 2; i++) {
                int idx = tid + (i << 8);
                int row = idx >> 2, ch = idx & 3;
                uint32_t sw = (uint32_t)(ch ^ ((row >> 1) & 3));
                cpasync16(sb + T * TILE_B + row * 64 + (sw << 4),
                          gsrc[T] + (size_t)row * K + k0 + ch * 8);
            }
        }
    };

    float acc[2][8][4] = {};

    #pragma unroll
    for (int s = 0; s < GSTAGES - 1; s++) { load_stage(s, s); cp_commit(); }

    for (int c = 0; c < chunks; c++) {
        cp_wait<GSTAGES - 2>();
        __syncthreads();
        const int cl = c + GSTAGES - 1;
        if (cl < chunks) load_stage(cl % GSTAGES, cl);
        cp_commit();

        const uint32_t sb = sbase + (c % GSTAGES) * STAGE_B;
        #pragma unroll
        for (int ks = 0; ks < 2; ks++) {
            uint32_t aF[2][4], bF[8][2];
            #pragma unroll
            for (int mt = 0; mt < 2; mt++) {
                int row = wm * 32 + mt * 16 + (lid & 15);
                int ch  = ks * 2 + (lid >> 4);
                uint32_t off = row * 64 + ((uint32_t)(ch ^ ((row >> 1) & 3)) << 4);
                ldsm_x4(sb + off, aF[mt][0], aF[mt][1], aF[mt][2], aF[mt][3]);
            }
            #pragma unroll
            for (int nt2 = 0; nt2 < 4; nt2++) {
                int row = wn * 64 + nt2 * 16 + (lid & 7) + ((lid >> 4) << 3);
                int ch  = ks * 2 + ((lid >> 3) & 1);
                uint32_t off = row * 64 + ((uint32_t)(ch ^ ((row >> 1) & 3)) << 4);
                ldsm_x4(sb + TILE_B + off,
                        bF[2*nt2][0], bF[2*nt2][1], bF[2*nt2+1][0], bF[2*nt2+1][1]);
            }
            #pragma unroll
            for (int mt = 0; mt < 2; mt++)
                #pragma unroll
                for (int nt = 0; nt < 8; nt++)
                    mma16816(acc[mt][nt], aF[mt], bF[nt]);
        }
    }

    const int gid = lid >> 2, tig = lid & 3;
    #pragma unroll
    for (int mt = 0; mt < 2; mt++) {
        #pragma unroll
        for (int nt = 0; nt < 8; nt++) {
            int r0  = mbase + wm * 32 + mt * 16 + gid;
            int col = nb0 + wn * 64 + nt * 8 + tig * 2;
            float2 bb = *reinterpret_cast<const float2*>(bias + col);
            float2 v0 = make_float2(acc[mt][nt][0] + bb.x, acc[mt][nt][1] + bb.y);
            float2 v1 = make_float2(acc[mt][nt][2] + bb.x, acc[mt][nt][3] + bb.y);
            *reinterpret_cast<float2*>(C + (size_t)r0 * ldc + col)       = v0;
            *reinterpret_cast<float2*>(C + (size_t)(r0 + 8) * ldc + col) = v1;
        }
    }
}

// ---------------- pair scoring: warp per pair -------------------------------
__global__ void pair_kernel(const int* __restrict__ dis, const int* __restrict__ mir,
                            const float* __restrict__ Wp, const float* __restrict__ bp,
                            float* __restrict__ out, int P)
{
    int warp = (blockIdx.x * blockDim.x + threadIdx.x) >> 5;
    int lane = threadIdx.x & 31;
    if (warp >= P) return;
    int di = dis[warp];
    int mi = mir[warp];
    const float* hd = g_h + (size_t)di * HIDD;
    const float* hm = g_h + (size_t)mi * HIDD;
    float s = 0.f;
    #pragma unroll 4
    for (int c = lane; c < HIDD; c += 32) {
        float a = hd[c], b = hm[c];
        s += a * Wp[c] + b * Wp[HIDD + c] + (a * b) * Wp[2 * HIDD + c];
    }
    #pragma unroll
    for (int o = 16; o; o >>= 1) s += __shfl_xor_sync(0xffffffffu, s, o);
    if (lane == 0) out[warp] = 1.f / (1.f + expf(-(s + bp[0])));
}

// ---------------- launch ----------------------------------------------------
extern "C" void kernel_launch(void* const* d_in, const int* in_sizes, int n_in,
                              void* d_out, int out_size)
{
    const float* d_sim    = (const float*)d_in[0];
    const float* m_sim    = (const float*)d_in[1];
    const int*   src      = (const int*)  d_in[2];
    const int*   dst      = (const int*)  d_in[3];
    const int*   diseases = (const int*)  d_in[4];
    const int*   mirnas   = (const int*)  d_in[5];
    const float* Wd       = (const float*)d_in[6];
    const float* Wm       = (const float*)d_in[7];
    const float* Wf       = (const float*)d_in[8];
    const float* bf       = (const float*)d_in[9];
    const float* Wp       = (const float*)d_in[10];
    const float* bp       = (const float*)d_in[11];
    float*       out      = (float*)d_out;

    const int E = in_sizes[2];
    const int P = in_sizes[4];

    float* hbuf = nullptr;
    __half *Bt = nullptr, *Fh = nullptr;
    cudaGetSymbolAddress((void**)&hbuf, g_h);
    cudaGetSymbolAddress((void**)&Bt, g_Bt);
    cudaGetSymbolAddress((void**)&Fh, g_Fh);

    cudaFuncSetAttribute(gemm_dm, cudaFuncAttributeMaxDynamicSharedMemorySize, GEMM_SMEM);
    cudaFuncSetAttribute(gemm_f,  cudaFuncAttributeMaxDynamicSharedMemorySize, GEMM_SMEM);

    // ---- graph prep
    zero_kernel<<<(NN + 255) / 256, 256>>>();
    deg_kernel<<<(E + 255) / 256, 256>>>(dst, E);
    normscan_kernel<<<1, 1024>>>();
    fill_kernel<<<(E + 255) / 256, 256>>>(src, dst, E);

    // ---- all weight transposes in one launch
    cvtBT_all<<<dim3(HIDD / 32, N_M / 32, 3), dim3(32, 8)>>>(Wd, Wm, Wf, Bt);

    // ---- fused d+m feature GEMM -> Fh[:, 0:512)
    gemm_dm<<<dim3(4, 96), 256, GEMM_SMEM>>>(d_sim, m_sim, Bt);

    // ---- K hops of normalized gather-sum (fp16 feat, fp32 accumulate)
    for (int hop = 0; hop < KHOP; hop++)
        hop_kernel<<<NN, 256>>>(hop * HIDD, (hop + 1) * HIDD);

    // ---- h = feat @ Wf + bf
    gemm_f<<<dim3(4, 96), 256, GEMM_SMEM>>>(
        Fh, Bt + (size_t)512 * (N_D + N_M), LDF, hbuf, HIDD, bf);

    // ---- pair prediction with sigmoid
    pair_kernel<<<(P * 32 + 255) / 256, 256>>>(diseases, mirnas, Wp, bp, out, P);
    (void)n_in; (void)out_size;
}